// round 1
// baseline (speedup 1.0000x reference)
#include <cuda_runtime.h>
#include <math.h>

#define NB 32
#define NS 256
#define NH 768
#define KC 32     // k-dim chunk
#define SCH 64    // s rows per chunk

// Normalized embeddings (scratch; device globals per allocation rules)
__device__ float g_Qn[NB * NS * NH];
__device__ float g_Kn[NB * NS * NH];
__device__ float g_w[NS];   // scale * exp(-alpha * d)

// ---------------------------------------------------------------------------
// Setup: decay table w[d] = exp(logit_scale) * exp(-softplus(alpha_raw) * d)
// ---------------------------------------------------------------------------
__global__ void setup_w_kernel(const float* __restrict__ alpha_raw,
                               const float* __restrict__ logit_scale) {
    float a = alpha_raw[0];
    float alpha = (a > 20.f) ? a : log1pf(expf(a));   // softplus
    float scale = expf(logit_scale[0]);
    int d = threadIdx.x;
    if (d < NS) g_w[d] = scale * expf(-alpha * (float)d);
}

// ---------------------------------------------------------------------------
// L2 normalize one row of H=768 per block (256 threads, 3 elems/thread)
// ---------------------------------------------------------------------------
__global__ void norm_kernel(const float* __restrict__ in, int which) {
    float* out = which ? g_Kn : g_Qn;
    int r = blockIdx.x;
    int tid = threadIdx.x;
    const float* x = in + (size_t)r * NH;
    float v0 = x[tid], v1 = x[tid + 256], v2 = x[tid + 512];
    float p = v0 * v0 + v1 * v1 + v2 * v2;
    #pragma unroll
    for (int o = 16; o; o >>= 1) p += __shfl_xor_sync(0xffffffffu, p, o);
    __shared__ float red[8];
    __shared__ float inv_s;
    if ((tid & 31) == 0) red[tid >> 5] = p;
    __syncthreads();
    if (tid == 0) {
        float t = 0.f;
        #pragma unroll
        for (int w = 0; w < 8; ++w) t += red[w];
        inv_s = 1.f / fmaxf(sqrtf(t), 1e-12f);
    }
    __syncthreads();
    float inv = inv_s;
    float* o = out + (size_t)r * NH;
    o[tid] = v0 * inv; o[tid + 256] = v1 * inv; o[tid + 512] = v2 * inv;
}

// ---------------------------------------------------------------------------
// Main: one CTA per (i,j) pair. For each 64-row s-chunk:
//   GEMM slab C[64,256] over K=768 (8x8 register tile per thread),
//   then fused decayed-softmax + score = sum_t p[s,t]*C[s,t].
// Deterministic single write of out[i,j].
// ---------------------------------------------------------------------------
__global__ void __launch_bounds__(256, 2)
li_main_kernel(const float* __restrict__ qmask, const float* __restrict__ kmask,
               float* __restrict__ out) {
    __shared__ float Ks[KC][NS + 1];    // [32][257] k-major -> conflict-free b loads
    __shared__ float Qs[KC][SCH + 1];   // [32][65]
    __shared__ float ws[NS];
    __shared__ float km[NS];
    __shared__ float qm[NS];
    __shared__ float warpRed[8];
    __shared__ float qsum_s;

    int i = blockIdx.x >> 5;
    int j = blockIdx.x & 31;
    int tid = threadIdx.x;
    int tx = tid & 31;     // lane
    int ty = tid >> 5;     // warp

    const float* Qb = g_Qn + (size_t)i * NS * NH;
    const float* Kb = g_Kn + (size_t)j * NS * NH;

    if (tid < NS) {
        ws[tid] = g_w[tid];
        km[tid] = kmask[j * NS + tid];
        qm[tid] = qmask[i * NS + tid];
    }
    __syncthreads();
    if (tid == 0) {
        float s = 0.f;
        for (int t = 0; t < NS; ++t) s += qm[t];
        qsum_s = s;
    }

    float totalScore = 0.f;

    for (int scix = 0; scix < NS / SCH; ++scix) {
        int s0 = scix * SCH;
        float acc[8][8];
        #pragma unroll
        for (int r = 0; r < 8; ++r)
            #pragma unroll
            for (int u = 0; u < 8; ++u) acc[r][u] = 0.f;

        for (int k0 = 0; k0 < NH; k0 += KC) {
            __syncthreads();
            // K tile: 256 t x 32 k (coalesced gmem, conflict-free smem write)
            #pragma unroll
            for (int it = 0; it < 32; ++it) {
                int t = ty + 8 * it;
                Ks[tx][t] = Kb[(size_t)t * NH + k0 + tx];
            }
            // Q tile: 64 s x 32 k
            #pragma unroll
            for (int it = 0; it < 8; ++it) {
                int s = ty + 8 * it;
                Qs[tx][s] = Qb[(size_t)(s0 + s) * NH + k0 + tx];
            }
            __syncthreads();
            #pragma unroll 4
            for (int kk = 0; kk < KC; ++kk) {
                float a[8], b[8];
                #pragma unroll
                for (int r = 0; r < 8; ++r) a[r] = Qs[kk][ty * 8 + r];   // broadcast
                #pragma unroll
                for (int u = 0; u < 8; ++u) b[u] = Ks[kk][tx + 32 * u]; // conflict-free
                #pragma unroll
                for (int r = 0; r < 8; ++r)
                    #pragma unroll
                    for (int u = 0; u < 8; ++u)
                        acc[r][u] = fmaf(a[r], b[u], acc[r][u]);
            }
        }

        // Fused decayed softmax + score for this warp's 8 rows.
        // Row s lives entirely in warp ty: lane tx holds t = tx + 32u.
        #pragma unroll
        for (int r = 0; r < 8; ++r) {
            int s = s0 + ty * 8 + r;
            float qms = qm[s];
            float l[8];
            float lmax = -INFINITY;
            #pragma unroll
            for (int u = 0; u < 8; ++u) {
                int t = tx + 32 * u;
                int d = s - t; d = d < 0 ? -d : d;
                bool v = (km[t] > 0.f) && (qms > 0.f);
                l[u] = v ? acc[r][u] * ws[d] : -INFINITY;
                lmax = fmaxf(lmax, l[u]);
            }
            #pragma unroll
            for (int o = 16; o; o >>= 1)
                lmax = fmaxf(lmax, __shfl_xor_sync(0xffffffffu, lmax, o));
            float se = 0.f, sec = 0.f;
            if (lmax > -INFINITY) {
                #pragma unroll
                for (int u = 0; u < 8; ++u) {
                    if (l[u] > -INFINITY) {
                        float e = __expf(l[u] - lmax);
                        se += e;
                        sec = fmaf(e, acc[r][u], sec);
                    }
                }
            }
            #pragma unroll
            for (int o = 16; o; o >>= 1) {
                se  += __shfl_xor_sync(0xffffffffu, se, o);
                sec += __shfl_xor_sync(0xffffffffu, sec, o);
            }
            float sc_v = (se > 0.f) ? (sec / se) : 0.f;
            totalScore += sc_v * qms;   // identical on all lanes
        }
    }

    __syncthreads();
    if (tx == 0) warpRed[ty] = totalScore;
    __syncthreads();
    if (tid == 0) {
        float tot = 0.f;
        #pragma unroll
        for (int w = 0; w < 8; ++w) tot += warpRed[w];
        out[i * NB + j] = tot / fmaxf(qsum_s, 1.f);
    }
}

extern "C" void kernel_launch(void* const* d_in, const int* in_sizes, int n_in,
                              void* d_out, int out_size) {
    const float* q           = (const float*)d_in[0];
    const float* k           = (const float*)d_in[1];
    const float* qmask       = (const float*)d_in[2];
    const float* kmask       = (const float*)d_in[3];
    const float* alpha_raw   = (const float*)d_in[4];
    const float* logit_scale = (const float*)d_in[5];
    float* out = (float*)d_out;

    setup_w_kernel<<<1, 256>>>(alpha_raw, logit_scale);
    norm_kernel<<<NB * NS, 256>>>(q, 0);
    norm_kernel<<<NB * NS, 256>>>(k, 1);
    li_main_kernel<<<NB * NB, 256>>>(qmask, kmask, out);
}

// round 3
// speedup vs baseline: 2.4029x; 2.4029x over previous
#include <cuda_runtime.h>
#include <cuda_bf16.h>
#include <math.h>
#include <stdint.h>

#define NB 32
#define NS 256
#define NH 768
#define KC 32
#define NCHUNK (NH / KC)   // 24
#define ROWB 80            // padded smem row stride: 64B data + 16B pad
#define MT 128

// ---------------- device scratch ----------------
__device__ __nv_bfloat16 g_Qhi[NB * NS * NH];
__device__ __nv_bfloat16 g_Qlo[NB * NS * NH];
__device__ __nv_bfloat16 g_Khi[NB * NS * NH];
__device__ __nv_bfloat16 g_Klo[NB * NS * NH];
__device__ float g_w[NS];
__device__ float g_partial[NB * NB * 2];

// ---------------- smem layout (per buffer 61440B, two buffers) ----------------
#define O_AH 0
#define O_AL 10240
#define O_BH 20480
#define O_BL 40960
#define BUF_SZ 61440
#define O_WS  (2 * BUF_SZ)           // 122880
#define O_KM  (O_WS + 1024)
#define O_QM  (O_KM + 1024)
#define O_RED (O_QM + 1024)
#define SMEM_NEED (O_RED + 64)

// ---------------- PTX helpers (base ISA only: sm_80-level) ----------------
__device__ __forceinline__ uint32_t smem_u32(const void* p) {
    uint32_t a;
    asm("{ .reg .u64 t; cvta.to.shared.u64 t, %1; cvt.u32.u64 %0, t; }" : "=r"(a) : "l"(p));
    return a;
}
__device__ __forceinline__ void cpasync16(uint32_t s, const void* g) {
    asm volatile("cp.async.cg.shared.global [%0], [%1], 16;" :: "r"(s), "l"(g));
}
#define CP_COMMIT() asm volatile("cp.async.commit_group;" ::: "memory")
#define CP_WAIT0()  asm volatile("cp.async.wait_group 0;" ::: "memory")
#define CP_WAIT1()  asm volatile("cp.async.wait_group 1;" ::: "memory")

__device__ __forceinline__ void ldsm4(uint32_t (&r)[4], uint32_t a) {
    asm volatile("ldmatrix.sync.aligned.m8n8.x4.shared.b16 {%0,%1,%2,%3}, [%4];"
                 : "=r"(r[0]), "=r"(r[1]), "=r"(r[2]), "=r"(r[3]) : "r"(a));
}
__device__ __forceinline__ void hmma(float* d, const uint32_t (&a)[4],
                                     uint32_t b0, uint32_t b1) {
    asm volatile(
        "mma.sync.aligned.m16n8k16.row.col.f32.bf16.bf16.f32 "
        "{%0,%1,%2,%3}, {%4,%5,%6,%7}, {%8,%9}, {%0,%1,%2,%3};"
        : "+f"(d[0]), "+f"(d[1]), "+f"(d[2]), "+f"(d[3])
        : "r"(a[0]), "r"(a[1]), "r"(a[2]), "r"(a[3]), "r"(b0), "r"(b1));
}

// ---------------------------------------------------------------------------
__global__ void setup_w_kernel(const float* __restrict__ alpha_raw,
                               const float* __restrict__ logit_scale) {
    float a = alpha_raw[0];
    float alpha = (a > 20.f) ? a : log1pf(expf(a));
    float scale = expf(logit_scale[0]);
    int d = threadIdx.x;
    if (d < NS) g_w[d] = scale * expf(-alpha * (float)d);
}

// L2-normalize one row of 768, split into bf16 hi + lo
__global__ void norm_split_kernel(const float* __restrict__ in, int which) {
    __nv_bfloat16* hi = which ? g_Khi : g_Qhi;
    __nv_bfloat16* lo = which ? g_Klo : g_Qlo;
    int r = blockIdx.x;
    int tid = threadIdx.x;
    const float* x = in + (size_t)r * NH;
    float v0 = x[tid], v1 = x[tid + 256], v2 = x[tid + 512];
    float p = v0 * v0 + v1 * v1 + v2 * v2;
    #pragma unroll
    for (int o = 16; o; o >>= 1) p += __shfl_xor_sync(0xffffffffu, p, o);
    __shared__ float red[8];
    __shared__ float inv_s;
    if ((tid & 31) == 0) red[tid >> 5] = p;
    __syncthreads();
    if (tid == 0) {
        float t = 0.f;
        #pragma unroll
        for (int w = 0; w < 8; ++w) t += red[w];
        inv_s = 1.f / fmaxf(sqrtf(t), 1e-12f);
    }
    __syncthreads();
    float inv = inv_s;
    size_t base = (size_t)r * NH;
    #pragma unroll
    for (int e = 0; e < 3; ++e) {
        float v = (e == 0 ? v0 : (e == 1 ? v1 : v2)) * inv;
        __nv_bfloat16 h = __float2bfloat16(v);
        float rem = v - __bfloat162float(h);
        hi[base + tid + e * 256] = h;
        lo[base + tid + e * 256] = __float2bfloat16(rem);
    }
}

// ---------------------------------------------------------------------------
// Main MMA kernel: blk = j*64 + i*2 + mt. CTA tile M=128 x N=256, K=768.
// sim = Ah*Bh + Ah*Bl + Al*Bh in fp32 HMMA accumulators (warp tile 16x256).
// ---------------------------------------------------------------------------
__device__ __forceinline__ void load_chunk(char* smem, uint32_t sb, int p, int c,
                                           int tid,
                                           const __nv_bfloat16* Qh, const __nv_bfloat16* Ql,
                                           const __nv_bfloat16* Kh, const __nv_bfloat16* Kl) {
    int k0 = c * KC;
    uint32_t bufb = sb + p * BUF_SZ;
    // A tiles: 128 rows x 32 elems (4x16B) for hi & lo
    #pragma unroll
    for (int it = 0; it < 2; ++it) {
        int x = tid + it * 256;       // 512 positions
        int r = x >> 2, g = x & 3;
        size_t go = (size_t)r * NH + k0 + g * 8;
        uint32_t so = (uint32_t)(r * ROWB + g * 16);
        cpasync16(bufb + O_AH + so, Qh + go);
        cpasync16(bufb + O_AL + so, Ql + go);
    }
    // B tiles: 256 rows
    #pragma unroll
    for (int it = 0; it < 4; ++it) {
        int x = tid + it * 256;       // 1024 positions
        int r = x >> 2, g = x & 3;
        size_t go = (size_t)r * NH + k0 + g * 8;
        uint32_t so = (uint32_t)(r * ROWB + g * 16);
        cpasync16(bufb + O_BH + so, Kh + go);
        cpasync16(bufb + O_BL + so, Kl + go);
    }
    CP_COMMIT();
}

__global__ void __launch_bounds__(256, 1)
li_mma_kernel(const float* __restrict__ qmask, const float* __restrict__ kmask) {
    extern __shared__ char smem[];
    uint32_t sb = smem_u32(smem);

    int tid = threadIdx.x, wid = tid >> 5, lid = tid & 31;
    int blk = blockIdx.x;
    int j = blk >> 6;
    int i = (blk >> 1) & 31;
    int mt = blk & 1;
    int s0 = mt * MT;

    float* ws = (float*)(smem + O_WS);
    float* km = (float*)(smem + O_KM);
    float* qm = (float*)(smem + O_QM);
    float* red = (float*)(smem + O_RED);
    ws[tid] = g_w[tid];
    km[tid] = kmask[j * NS + tid];
    qm[tid] = qmask[i * NS + tid];

    const __nv_bfloat16* Qh = g_Qhi + ((size_t)i * NS + s0) * NH;
    const __nv_bfloat16* Ql = g_Qlo + ((size_t)i * NS + s0) * NH;
    const __nv_bfloat16* Kh = g_Khi + (size_t)j * NS * NH;
    const __nv_bfloat16* Kl = g_Klo + (size_t)j * NS * NH;

    float acc[32][4];
    #pragma unroll
    for (int nf = 0; nf < 32; ++nf)
        #pragma unroll
        for (int u = 0; u < 4; ++u) acc[nf][u] = 0.f;

    // ldmatrix lane addressing (precomputed)
    // A (m16k16): lane -> row = lane%16, k-half = lane/16
    uint32_t a_off = (uint32_t)((wid * 16 + (lid & 15)) * ROWB + ((lid >> 4) << 4));
    // B (n16k16 as x4): lanes 0-7: n0-7 k0; 8-15: n0-7 k16B; 16-23: n8-15 k0; 24-31: n8-15 k16B
    uint32_t b_row = ((lid >> 4) & 1) * 8 + (lid & 7);
    uint32_t b_off = (uint32_t)(b_row * ROWB + ((lid >> 3) & 1) * 16);

    load_chunk(smem, sb, 0, 0, tid, Qh, Ql, Kh, Kl);

    for (int c = 0; c < NCHUNK; ++c) {
        int p = c & 1;
        if (c + 1 < NCHUNK) {
            load_chunk(smem, sb, (c + 1) & 1, c + 1, tid, Qh, Ql, Kh, Kl);
            CP_WAIT1();
        } else {
            CP_WAIT0();
        }
        __syncthreads();

        uint32_t base = sb + p * BUF_SZ;
        #pragma unroll
        for (int ks = 0; ks < 2; ++ks) {
            uint32_t Ah[4], Al[4];
            ldsm4(Ah, base + O_AH + a_off + ks * 32);
            ldsm4(Al, base + O_AL + a_off + ks * 32);
            #pragma unroll
            for (int np = 0; np < 16; ++np) {
                uint32_t Bh[4], Bl[4];
                uint32_t baddr = base + O_BH + np * 16 * ROWB + b_off + ks * 32;
                ldsm4(Bh, baddr);
                ldsm4(Bl, baddr + (O_BL - O_BH));
                hmma(acc[2 * np],     Ah, Bh[0], Bh[1]);
                hmma(acc[2 * np + 1], Ah, Bh[2], Bh[3]);
                hmma(acc[2 * np],     Ah, Bl[0], Bl[1]);
                hmma(acc[2 * np + 1], Ah, Bl[2], Bl[3]);
                hmma(acc[2 * np],     Al, Bh[0], Bh[1]);
                hmma(acc[2 * np + 1], Al, Bh[2], Bh[3]);
            }
        }
        __syncthreads();   // protect buffer p before chunk c+2 loads overwrite it
    }

    // ---- fused epilogue: warp owns rows [wid*16, wid*16+16) ----
    // acc frag layout: acc[nf][0,1] -> row r0 = wid*16+lid/4, cols nf*8+2*(lid%3=lid&3)+{0,1}
    //                  acc[nf][2,3] -> row r0+8
    int cb = 2 * (lid & 3);
    float warp_score = 0.f;
    #pragma unroll
    for (int half = 0; half < 2; ++half) {
        int sl = wid * 16 + (lid >> 2) + half * 8;  // 0..127 within tile
        int s = s0 + sl;
        float qms = qm[s];
        float m = -INFINITY;
        #pragma unroll
        for (int nf = 0; nf < 32; ++nf) {
            #pragma unroll
            for (int cc = 0; cc < 2; ++cc) {
                int t = nf * 8 + cb + cc;
                if (km[t] > 0.f) {
                    float sim = acc[nf][half * 2 + cc];
                    int d = s - t; d = d < 0 ? -d : d;
                    float l = sim * ws[d];
                    m = fmaxf(m, l);
                }
            }
        }
        m = fmaxf(m, __shfl_xor_sync(0xffffffffu, m, 1));
        m = fmaxf(m, __shfl_xor_sync(0xffffffffu, m, 2));
        float se = 0.f, sec = 0.f;
        if (m > -INFINITY) {
            #pragma unroll
            for (int nf = 0; nf < 32; ++nf) {
                #pragma unroll
                for (int cc = 0; cc < 2; ++cc) {
                    int t = nf * 8 + cb + cc;
                    if (km[t] > 0.f) {
                        float sim = acc[nf][half * 2 + cc];
                        int d = s - t; d = d < 0 ? -d : d;
                        float e = __expf(sim * ws[d] - m);
                        se += e;
                        sec = fmaf(e, sim, sec);
                    }
                }
            }
        }
        se  += __shfl_xor_sync(0xffffffffu, se, 1);
        se  += __shfl_xor_sync(0xffffffffu, se, 2);
        sec += __shfl_xor_sync(0xffffffffu, sec, 1);
        sec += __shfl_xor_sync(0xffffffffu, sec, 2);
        if (se > 0.f && qms > 0.f)
            warp_score += (sec / se) * qms * 0.25f;  // 4 lanes replicate each row
    }
    // warp-wide sum
    #pragma unroll
    for (int o = 16; o; o >>= 1)
        warp_score += __shfl_xor_sync(0xffffffffu, warp_score, o);
    if (lid == 0) red[wid] = warp_score;
    __syncthreads();
    if (tid == 0) {
        float tot = 0.f;
        #pragma unroll
        for (int w = 0; w < 8; ++w) tot += red[w];
        g_partial[blk] = tot;
    }
}

// ---------------------------------------------------------------------------
__global__ void reduce_kernel(const float* __restrict__ qmask, float* __restrict__ out) {
    int i = blockIdx.x;
    int tid = threadIdx.x;
    float v = qmask[i * NS + tid];
    #pragma unroll
    for (int o = 16; o; o >>= 1) v += __shfl_xor_sync(0xffffffffu, v, o);
    __shared__ float red[8];
    __shared__ float qsum_s;
    if ((tid & 31) == 0) red[tid >> 5] = v;
    __syncthreads();
    if (tid == 0) {
        float t = 0.f;
        #pragma unroll
        for (int w = 0; w < 8; ++w) t += red[w];
        qsum_s = fmaxf(t, 1.f);
    }
    __syncthreads();
    if (tid < NB) {
        int jj = tid;
        float val = g_partial[jj * 64 + i * 2] + g_partial[jj * 64 + i * 2 + 1];
        out[i * NB + jj] = val / qsum_s;
    }
}

extern "C" void kernel_launch(void* const* d_in, const int* in_sizes, int n_in,
                              void* d_out, int out_size) {
    const float* q           = (const float*)d_in[0];
    const float* k           = (const float*)d_in[1];
    const float* qmask       = (const float*)d_in[2];
    const float* kmask       = (const float*)d_in[3];
    const float* alpha_raw   = (const float*)d_in[4];
    const float* logit_scale = (const float*)d_in[5];
    float* out = (float*)d_out;

    cudaFuncSetAttribute(li_mma_kernel, cudaFuncAttributeMaxDynamicSharedMemorySize, SMEM_NEED);

    setup_w_kernel<<<1, 256>>>(alpha_raw, logit_scale);
    norm_split_kernel<<<NB * NS, 256>>>(q, 0);
    norm_split_kernel<<<NB * NS, 256>>>(k, 1);
    li_mma_kernel<<<NB * NB * 2, 256, SMEM_NEED>>>(qmask, kmask);
    reduce_kernel<<<NB, 256>>>(qmask, out);
}

// round 4
// speedup vs baseline: 3.2213x; 1.3406x over previous
#include <cuda_runtime.h>
#include <cuda_fp16.h>
#include <math.h>
#include <stdint.h>

#define NB 32
#define NS 256
#define NH 768
#define KC 32
#define NCHUNK (NH / KC)   // 24
#define ROWB 80            // padded smem row stride: 64B data + 16B pad
#define MT 128

// ---------------- device scratch ----------------
__device__ __half g_Qhi[NB * NS * NH];
__device__ __half g_Qlo[NB * NS * NH];
__device__ __half g_Kh [NB * NS * NH];
__device__ float g_w[NS];
__device__ float g_partial[NB * NB * 2];

// ---------------- smem layout (per buffer 40960B, two buffers) ----------------
#define O_AH 0
#define O_AL 10240
#define O_B  20480
#define BUF_SZ 40960
#define O_WS  (2 * BUF_SZ)           // 81920
#define O_KM  (O_WS + 1024)
#define O_QM  (O_KM + 1024)
#define O_RED (O_QM + 1024)
#define SMEM_NEED (O_RED + 64)

// ---------------- PTX helpers (base ISA only) ----------------
__device__ __forceinline__ uint32_t smem_u32(const void* p) {
    uint32_t a;
    asm("{ .reg .u64 t; cvta.to.shared.u64 t, %1; cvt.u32.u64 %0, t; }" : "=r"(a) : "l"(p));
    return a;
}
__device__ __forceinline__ void cpasync16(uint32_t s, const void* g) {
    asm volatile("cp.async.cg.shared.global [%0], [%1], 16;" :: "r"(s), "l"(g));
}
#define CP_COMMIT() asm volatile("cp.async.commit_group;" ::: "memory")
#define CP_WAIT0()  asm volatile("cp.async.wait_group 0;" ::: "memory")
#define CP_WAIT1()  asm volatile("cp.async.wait_group 1;" ::: "memory")

__device__ __forceinline__ void ldsm4(uint32_t (&r)[4], uint32_t a) {
    asm volatile("ldmatrix.sync.aligned.m8n8.x4.shared.b16 {%0,%1,%2,%3}, [%4];"
                 : "=r"(r[0]), "=r"(r[1]), "=r"(r[2]), "=r"(r[3]) : "r"(a));
}
__device__ __forceinline__ void hmma(float* d, const uint32_t (&a)[4],
                                     uint32_t b0, uint32_t b1) {
    asm volatile(
        "mma.sync.aligned.m16n8k16.row.col.f32.f16.f16.f32 "
        "{%0,%1,%2,%3}, {%4,%5,%6,%7}, {%8,%9}, {%0,%1,%2,%3};"
        : "+f"(d[0]), "+f"(d[1]), "+f"(d[2]), "+f"(d[3])
        : "r"(a[0]), "r"(a[1]), "r"(a[2]), "r"(a[3]), "r"(b0), "r"(b1));
}

// ---------------------------------------------------------------------------
__global__ void setup_w_kernel(const float* __restrict__ alpha_raw,
                               const float* __restrict__ logit_scale) {
    float a = alpha_raw[0];
    float alpha = (a > 20.f) ? a : log1pf(expf(a));
    float scale = expf(logit_scale[0]);
    int d = threadIdx.x;
    if (d < NS) g_w[d] = scale * expf(-alpha * (float)d);
}

// L2-normalize one row of 768.
// which=0 (Q): split into fp16 hi + fp16 lo (A-side effectively exact).
// which=1 (K): single fp16.
__global__ void norm_split_kernel(const float* __restrict__ in, int which) {
    int r = blockIdx.x;
    int tid = threadIdx.x;
    const float* x = in + (size_t)r * NH;
    float v0 = x[tid], v1 = x[tid + 256], v2 = x[tid + 512];
    float p = v0 * v0 + v1 * v1 + v2 * v2;
    #pragma unroll
    for (int o = 16; o; o >>= 1) p += __shfl_xor_sync(0xffffffffu, p, o);
    __shared__ float red[8];
    __shared__ float inv_s;
    if ((tid & 31) == 0) red[tid >> 5] = p;
    __syncthreads();
    if (tid == 0) {
        float t = 0.f;
        #pragma unroll
        for (int w = 0; w < 8; ++w) t += red[w];
        inv_s = 1.f / fmaxf(sqrtf(t), 1e-12f);
    }
    __syncthreads();
    float inv = inv_s;
    size_t base = (size_t)r * NH;
    #pragma unroll
    for (int e = 0; e < 3; ++e) {
        float v = (e == 0 ? v0 : (e == 1 ? v1 : v2)) * inv;
        if (which) {
            g_Kh[base + tid + e * 256] = __float2half(v);
        } else {
            __half h = __float2half(v);
            float rem = v - __half2float(h);
            g_Qhi[base + tid + e * 256] = h;
            g_Qlo[base + tid + e * 256] = __float2half(rem);
        }
    }
}

// ---------------------------------------------------------------------------
// Main MMA kernel: blk = j*64 + i*2 + mt. CTA tile M=128 x N=256, K=768.
// sim = Ah*B + Al*B in fp32 HMMA accumulators (warp tile 16x256).
// ---------------------------------------------------------------------------
__device__ __forceinline__ void load_chunk(uint32_t sb, int p, int c, int tid,
                                           const __half* Qh, const __half* Ql,
                                           const __half* Kh) {
    int k0 = c * KC;
    uint32_t bufb = sb + p * BUF_SZ;
    // A tiles: 128 rows x 32 elems (4x16B) for hi & lo
    #pragma unroll
    for (int it = 0; it < 2; ++it) {
        int x = tid + it * 256;       // 512 positions
        int r = x >> 2, g = x & 3;
        size_t go = (size_t)r * NH + k0 + g * 8;
        uint32_t so = (uint32_t)(r * ROWB + g * 16);
        cpasync16(bufb + O_AH + so, Qh + go);
        cpasync16(bufb + O_AL + so, Ql + go);
    }
    // B tile: 256 rows (single fp16 piece)
    #pragma unroll
    for (int it = 0; it < 4; ++it) {
        int x = tid + it * 256;       // 1024 positions
        int r = x >> 2, g = x & 3;
        size_t go = (size_t)r * NH + k0 + g * 8;
        uint32_t so = (uint32_t)(r * ROWB + g * 16);
        cpasync16(bufb + O_B + so, Kh + go);
    }
    CP_COMMIT();
}

__global__ void __launch_bounds__(256, 1)
li_mma_kernel(const float* __restrict__ qmask, const float* __restrict__ kmask) {
    extern __shared__ char smem[];
    uint32_t sb = smem_u32(smem);

    int tid = threadIdx.x, wid = tid >> 5, lid = tid & 31;
    int blk = blockIdx.x;
    int j = blk >> 6;
    int i = (blk >> 1) & 31;
    int mt = blk & 1;
    int s0 = mt * MT;

    float* ws = (float*)(smem + O_WS);
    float* km = (float*)(smem + O_KM);
    float* qm = (float*)(smem + O_QM);
    float* red = (float*)(smem + O_RED);
    ws[tid] = g_w[tid];
    km[tid] = kmask[j * NS + tid];
    qm[tid] = qmask[i * NS + tid];

    const __half* Qh = g_Qhi + ((size_t)i * NS + s0) * NH;
    const __half* Ql = g_Qlo + ((size_t)i * NS + s0) * NH;
    const __half* Kh = g_Kh  + (size_t)j * NS * NH;

    float acc[32][4];
    #pragma unroll
    for (int nf = 0; nf < 32; ++nf)
        #pragma unroll
        for (int u = 0; u < 4; ++u) acc[nf][u] = 0.f;

    // ldmatrix lane addressing
    uint32_t a_off = (uint32_t)((wid * 16 + (lid & 15)) * ROWB + ((lid >> 4) << 4));
    uint32_t b_row = ((lid >> 4) & 1) * 8 + (lid & 7);
    uint32_t b_off = (uint32_t)(b_row * ROWB + ((lid >> 3) & 1) * 16);

    load_chunk(sb, 0, 0, tid, Qh, Ql, Kh);

    for (int c = 0; c < NCHUNK; ++c) {
        int p = c & 1;
        if (c + 1 < NCHUNK) {
            load_chunk(sb, (c + 1) & 1, c + 1, tid, Qh, Ql, Kh);
            CP_WAIT1();
        } else {
            CP_WAIT0();
        }
        __syncthreads();

        uint32_t base = sb + p * BUF_SZ;
        #pragma unroll
        for (int ks = 0; ks < 2; ++ks) {
            uint32_t Ah[4], Al[4];
            ldsm4(Ah, base + O_AH + a_off + ks * 32);
            ldsm4(Al, base + O_AL + a_off + ks * 32);
            #pragma unroll
            for (int np = 0; np < 16; ++np) {
                uint32_t B[4];
                ldsm4(B, base + O_B + np * 16 * ROWB + b_off + ks * 32);
                hmma(acc[2 * np],     Ah, B[0], B[1]);
                hmma(acc[2 * np + 1], Ah, B[2], B[3]);
                hmma(acc[2 * np],     Al, B[0], B[1]);
                hmma(acc[2 * np + 1], Al, B[2], B[3]);
            }
        }
        __syncthreads();   // protect buffer p before chunk c+2 loads overwrite it
    }

    // ---- fused epilogue: warp owns rows [wid*16, wid*16+16) ----
    int cb = 2 * (lid & 3);
    float warp_score = 0.f;
    #pragma unroll
    for (int half = 0; half < 2; ++half) {
        int sl = wid * 16 + (lid >> 2) + half * 8;
        int s = s0 + sl;
        float qms = qm[s];
        float m = -INFINITY;
        #pragma unroll
        for (int nf = 0; nf < 32; ++nf) {
            #pragma unroll
            for (int cc = 0; cc < 2; ++cc) {
                int t = nf * 8 + cb + cc;
                if (km[t] > 0.f) {
                    float sim = acc[nf][half * 2 + cc];
                    int d = s - t; d = d < 0 ? -d : d;
                    float l = sim * ws[d];
                    m = fmaxf(m, l);
                }
            }
        }
        m = fmaxf(m, __shfl_xor_sync(0xffffffffu, m, 1));
        m = fmaxf(m, __shfl_xor_sync(0xffffffffu, m, 2));
        float se = 0.f, sec = 0.f;
        if (m > -INFINITY) {
            #pragma unroll
            for (int nf = 0; nf < 32; ++nf) {
                #pragma unroll
                for (int cc = 0; cc < 2; ++cc) {
                    int t = nf * 8 + cb + cc;
                    if (km[t] > 0.f) {
                        float sim = acc[nf][half * 2 + cc];
                        int d = s - t; d = d < 0 ? -d : d;
                        float e = __expf(sim * ws[d] - m);
                        se += e;
                        sec = fmaf(e, sim, sec);
                    }
                }
            }
        }
        se  += __shfl_xor_sync(0xffffffffu, se, 1);
        se  += __shfl_xor_sync(0xffffffffu, se, 2);
        sec += __shfl_xor_sync(0xffffffffu, sec, 1);
        sec += __shfl_xor_sync(0xffffffffu, sec, 2);
        if (se > 0.f && qms > 0.f)
            warp_score += (sec / se) * qms * 0.25f;  // 4 lanes replicate each row
    }
    #pragma unroll
    for (int o = 16; o; o >>= 1)
        warp_score += __shfl_xor_sync(0xffffffffu, warp_score, o);
    if (lid == 0) red[wid] = warp_score;
    __syncthreads();
    if (tid == 0) {
        float tot = 0.f;
        #pragma unroll
        for (int w = 0; w < 8; ++w) tot += red[w];
        g_partial[blk] = tot;
    }
}

// ---------------------------------------------------------------------------
__global__ void reduce_kernel(const float* __restrict__ qmask, float* __restrict__ out) {
    int i = blockIdx.x;
    int tid = threadIdx.x;
    float v = qmask[i * NS + tid];
    #pragma unroll
    for (int o = 16; o; o >>= 1) v += __shfl_xor_sync(0xffffffffu, v, o);
    __shared__ float red[8];
    __shared__ float qsum_s;
    if ((tid & 31) == 0) red[tid >> 5] = v;
    __syncthreads();
    if (tid == 0) {
        float t = 0.f;
        #pragma unroll
        for (int w = 0; w < 8; ++w) t += red[w];
        qsum_s = fmaxf(t, 1.f);
    }
    __syncthreads();
    if (tid < NB) {
        int jj = tid;
        float val = g_partial[jj * 64 + i * 2] + g_partial[jj * 64 + i * 2 + 1];
        out[i * NB + jj] = val / qsum_s;
    }
}

extern "C" void kernel_launch(void* const* d_in, const int* in_sizes, int n_in,
                              void* d_out, int out_size) {
    const float* q           = (const float*)d_in[0];
    const float* k           = (const float*)d_in[1];
    const float* qmask       = (const float*)d_in[2];
    const float* kmask       = (const float*)d_in[3];
    const float* alpha_raw   = (const float*)d_in[4];
    const float* logit_scale = (const float*)d_in[5];
    float* out = (float*)d_out;

    cudaFuncSetAttribute(li_mma_kernel, cudaFuncAttributeMaxDynamicSharedMemorySize, SMEM_NEED);

    setup_w_kernel<<<1, 256>>>(alpha_raw, logit_scale);
    norm_split_kernel<<<NB * NS, 256>>>(q, 0);
    norm_split_kernel<<<NB * NS, 256>>>(k, 1);
    li_mma_kernel<<<NB * NB * 2, 256, SMEM_NEED>>>(qmask, kmask);
    reduce_kernel<<<NB, 256>>>(qmask, out);
}

// round 5
// speedup vs baseline: 4.2171x; 1.3091x over previous
#include <cuda_runtime.h>
#include <cuda_fp16.h>
#include <math.h>
#include <stdint.h>

#define NB 32
#define NS 256
#define NH 768
#define KC 32
#define NCHUNK (NH / KC)   // 24
#define ROWB 80            // padded smem row stride: 64B data + 16B pad
#define MT 128

// ---------------- device scratch ----------------
__device__ __half g_Qh[NB * NS * NH];
__device__ __half g_Kh[NB * NS * NH];
__device__ float g_w[NS];
__device__ float g_partial[NB * NB * 2];

// ---------------- smem layout (per buffer 30720B, two buffers) ----------------
#define O_A  0
#define O_B  10240
#define BUF_SZ 30720
#define O_WS  (2 * BUF_SZ)           // 61440
#define O_KM  (O_WS + 1024)
#define O_QM  (O_KM + 1024)
#define O_RED (O_QM + 1024)
#define SMEM_NEED (O_RED + 64)

// ---------------- PTX helpers (base ISA only) ----------------
__device__ __forceinline__ uint32_t smem_u32(const void* p) {
    uint32_t a;
    asm("{ .reg .u64 t; cvta.to.shared.u64 t, %1; cvt.u32.u64 %0, t; }" : "=r"(a) : "l"(p));
    return a;
}
__device__ __forceinline__ void cpasync16(uint32_t s, const void* g) {
    asm volatile("cp.async.cg.shared.global [%0], [%1], 16;" :: "r"(s), "l"(g));
}
#define CP_COMMIT() asm volatile("cp.async.commit_group;" ::: "memory")
#define CP_WAIT0()  asm volatile("cp.async.wait_group 0;" ::: "memory")
#define CP_WAIT1()  asm volatile("cp.async.wait_group 1;" ::: "memory")

__device__ __forceinline__ void ldsm4(uint32_t (&r)[4], uint32_t a) {
    asm volatile("ldmatrix.sync.aligned.m8n8.x4.shared.b16 {%0,%1,%2,%3}, [%4];"
                 : "=r"(r[0]), "=r"(r[1]), "=r"(r[2]), "=r"(r[3]) : "r"(a));
}
__device__ __forceinline__ void hmma(float* d, const uint32_t (&a)[4],
                                     uint32_t b0, uint32_t b1) {
    asm volatile(
        "mma.sync.aligned.m16n8k16.row.col.f32.f16.f16.f32 "
        "{%0,%1,%2,%3}, {%4,%5,%6,%7}, {%8,%9}, {%0,%1,%2,%3};"
        : "+f"(d[0]), "+f"(d[1]), "+f"(d[2]), "+f"(d[3])
        : "r"(a[0]), "r"(a[1]), "r"(a[2]), "r"(a[3]), "r"(b0), "r"(b1));
}

// ---------------------------------------------------------------------------
__global__ void setup_w_kernel(const float* __restrict__ alpha_raw,
                               const float* __restrict__ logit_scale) {
    float a = alpha_raw[0];
    float alpha = (a > 20.f) ? a : log1pf(expf(a));
    float scale = expf(logit_scale[0]);
    int d = threadIdx.x;
    if (d < NS) g_w[d] = scale * expf(-alpha * (float)d);
}

// L2-normalize one row of 768 -> single fp16
__global__ void norm_kernel(const float* __restrict__ in, int which) {
    __half* dst = which ? g_Kh : g_Qh;
    int r = blockIdx.x;
    int tid = threadIdx.x;
    const float* x = in + (size_t)r * NH;
    float v0 = x[tid], v1 = x[tid + 256], v2 = x[tid + 512];
    float p = v0 * v0 + v1 * v1 + v2 * v2;
    #pragma unroll
    for (int o = 16; o; o >>= 1) p += __shfl_xor_sync(0xffffffffu, p, o);
    __shared__ float red[8];
    __shared__ float inv_s;
    if ((tid & 31) == 0) red[tid >> 5] = p;
    __syncthreads();
    if (tid == 0) {
        float t = 0.f;
        #pragma unroll
        for (int w = 0; w < 8; ++w) t += red[w];
        inv_s = 1.f / fmaxf(sqrtf(t), 1e-12f);
    }
    __syncthreads();
    float inv = inv_s;
    size_t base = (size_t)r * NH;
    dst[base + tid]       = __float2half(v0 * inv);
    dst[base + tid + 256] = __float2half(v1 * inv);
    dst[base + tid + 512] = __float2half(v2 * inv);
}

// ---------------------------------------------------------------------------
// Main MMA kernel: blk = j*64 + i*2 + mt. CTA tile M=128 x N=256, K=768.
// sim = A*B (single fp16 product), fp32 HMMA accumulators, warp tile 16x256.
// ---------------------------------------------------------------------------
__device__ __forceinline__ void load_chunk(uint32_t sb, int p, int c, int tid,
                                           const __half* Qp, const __half* Kp) {
    int k0 = c * KC;
    uint32_t bufb = sb + p * BUF_SZ;
    // A tile: 128 rows x 32 elems (4x16B)
    #pragma unroll
    for (int it = 0; it < 2; ++it) {
        int x = tid + it * 256;       // 512 positions
        int r = x >> 2, g = x & 3;
        size_t go = (size_t)r * NH + k0 + g * 8;
        uint32_t so = (uint32_t)(r * ROWB + g * 16);
        cpasync16(bufb + O_A + so, Qp + go);
    }
    // B tile: 256 rows
    #pragma unroll
    for (int it = 0; it < 4; ++it) {
        int x = tid + it * 256;       // 1024 positions
        int r = x >> 2, g = x & 3;
        size_t go = (size_t)r * NH + k0 + g * 8;
        uint32_t so = (uint32_t)(r * ROWB + g * 16);
        cpasync16(bufb + O_B + so, Kp + go);
    }
    CP_COMMIT();
}

__global__ void __launch_bounds__(256, 1)
li_mma_kernel(const float* __restrict__ qmask, const float* __restrict__ kmask) {
    extern __shared__ char smem[];
    uint32_t sb = smem_u32(smem);

    int tid = threadIdx.x, wid = tid >> 5, lid = tid & 31;
    int blk = blockIdx.x;
    int j = blk >> 6;
    int i = (blk >> 1) & 31;
    int mt = blk & 1;
    int s0 = mt * MT;

    float* ws = (float*)(smem + O_WS);
    float* km = (float*)(smem + O_KM);
    float* qm = (float*)(smem + O_QM);
    float* red = (float*)(smem + O_RED);
    ws[tid] = g_w[tid];
    km[tid] = kmask[j * NS + tid];
    qm[tid] = qmask[i * NS + tid];

    const __half* Qp = g_Qh + ((size_t)i * NS + s0) * NH;
    const __half* Kp = g_Kh + (size_t)j * NS * NH;

    float acc[32][4];
    #pragma unroll
    for (int nf = 0; nf < 32; ++nf)
        #pragma unroll
        for (int u = 0; u < 4; ++u) acc[nf][u] = 0.f;

    // ldmatrix lane addressing
    uint32_t a_off = (uint32_t)((wid * 16 + (lid & 15)) * ROWB + ((lid >> 4) << 4));
    uint32_t b_row = ((lid >> 4) & 1) * 8 + (lid & 7);
    uint32_t b_off = (uint32_t)(b_row * ROWB + ((lid >> 3) & 1) * 16);

    load_chunk(sb, 0, 0, tid, Qp, Kp);

    for (int c = 0; c < NCHUNK; ++c) {
        int p = c & 1;
        if (c + 1 < NCHUNK) {
            load_chunk(sb, (c + 1) & 1, c + 1, tid, Qp, Kp);
            CP_WAIT1();
        } else {
            CP_WAIT0();
        }
        __syncthreads();

        uint32_t base = sb + p * BUF_SZ;
        #pragma unroll
        for (int ks = 0; ks < 2; ++ks) {
            uint32_t A[4];
            ldsm4(A, base + O_A + a_off + ks * 32);
            #pragma unroll
            for (int np = 0; np < 16; ++np) {
                uint32_t B[4];
                ldsm4(B, base + O_B + np * 16 * ROWB + b_off + ks * 32);
                hmma(acc[2 * np],     A, B[0], B[1]);
                hmma(acc[2 * np + 1], A, B[2], B[3]);
            }
        }
        __syncthreads();   // protect buffer p before chunk c+2 loads overwrite it
    }

    // ---- fused epilogue: warp owns rows [wid*16, wid*16+16) ----
    int cb = 2 * (lid & 3);
    float warp_score = 0.f;
    #pragma unroll
    for (int half = 0; half < 2; ++half) {
        int sl = wid * 16 + (lid >> 2) + half * 8;
        int s = s0 + sl;
        float qms = qm[s];
        float m = -INFINITY;
        #pragma unroll
        for (int nf = 0; nf < 32; ++nf) {
            #pragma unroll
            for (int cc = 0; cc < 2; ++cc) {
                int t = nf * 8 + cb + cc;
                if (km[t] > 0.f) {
                    float sim = acc[nf][half * 2 + cc];
                    int d = s - t; d = d < 0 ? -d : d;
                    float l = sim * ws[d];
                    m = fmaxf(m, l);
                }
            }
        }
        m = fmaxf(m, __shfl_xor_sync(0xffffffffu, m, 1));
        m = fmaxf(m, __shfl_xor_sync(0xffffffffu, m, 2));
        float se = 0.f, sec = 0.f;
        if (m > -INFINITY) {
            #pragma unroll
            for (int nf = 0; nf < 32; ++nf) {
                #pragma unroll
                for (int cc = 0; cc < 2; ++cc) {
                    int t = nf * 8 + cb + cc;
                    if (km[t] > 0.f) {
                        float sim = acc[nf][half * 2 + cc];
                        int d = s - t; d = d < 0 ? -d : d;
                        float e = __expf(sim * ws[d] - m);
                        se += e;
                        sec = fmaf(e, sim, sec);
                    }
                }
            }
        }
        se  += __shfl_xor_sync(0xffffffffu, se, 1);
        se  += __shfl_xor_sync(0xffffffffu, se, 2);
        sec += __shfl_xor_sync(0xffffffffu, sec, 1);
        sec += __shfl_xor_sync(0xffffffffu, sec, 2);
        if (se > 0.f && qms > 0.f)
            warp_score += (sec / se) * qms * 0.25f;  // 4 lanes replicate each row
    }
    #pragma unroll
    for (int o = 16; o; o >>= 1)
        warp_score += __shfl_xor_sync(0xffffffffu, warp_score, o);
    if (lid == 0) red[wid] = warp_score;
    __syncthreads();
    if (tid == 0) {
        float tot = 0.f;
        #pragma unroll
        for (int w = 0; w < 8; ++w) tot += red[w];
        g_partial[blk] = tot;
    }
}

// ---------------------------------------------------------------------------
__global__ void reduce_kernel(const float* __restrict__ qmask, float* __restrict__ out) {
    int i = blockIdx.x;
    int tid = threadIdx.x;
    float v = qmask[i * NS + tid];
    #pragma unroll
    for (int o = 16; o; o >>= 1) v += __shfl_xor_sync(0xffffffffu, v, o);
    __shared__ float red[8];
    __shared__ float qsum_s;
    if ((tid & 31) == 0) red[tid >> 5] = v;
    __syncthreads();
    if (tid == 0) {
        float t = 0.f;
        #pragma unroll
        for (int w = 0; w < 8; ++w) t += red[w];
        qsum_s = fmaxf(t, 1.f);
    }
    __syncthreads();
    if (tid < NB) {
        int jj = tid;
        float val = g_partial[jj * 64 + i * 2] + g_partial[jj * 64 + i * 2 + 1];
        out[i * NB + jj] = val / qsum_s;
    }
}

extern "C" void kernel_launch(void* const* d_in, const int* in_sizes, int n_in,
                              void* d_out, int out_size) {
    const float* q           = (const float*)d_in[0];
    const float* k           = (const float*)d_in[1];
    const float* qmask       = (const float*)d_in[2];
    const float* kmask       = (const float*)d_in[3];
    const float* alpha_raw   = (const float*)d_in[4];
    const float* logit_scale = (const float*)d_in[5];
    float* out = (float*)d_out;

    cudaFuncSetAttribute(li_mma_kernel, cudaFuncAttributeMaxDynamicSharedMemorySize, SMEM_NEED);

    setup_w_kernel<<<1, 256>>>(alpha_raw, logit_scale);
    norm_kernel<<<NB * NS, 256>>>(q, 0);
    norm_kernel<<<NB * NS, 256>>>(k, 1);
    li_mma_kernel<<<NB * NB * 2, 256, SMEM_NEED>>>(qmask, kmask);
    reduce_kernel<<<NB, 256>>>(qmask, out);
}

// round 6
// speedup vs baseline: 5.5560x; 1.3175x over previous
#include <cuda_runtime.h>
#include <cuda_fp16.h>
#include <math.h>
#include <stdint.h>

#define NB 32
#define NS 256
#define NH 768
#define KC 32
#define NCHUNK (NH / KC)   // 24
#define ROWB 80            // padded smem row stride: 64B data + 16B pad
#define MT_M 64            // M rows per CTA
#define NMT 4              // m-tiles per (i,j)

// ---------------- device scratch ----------------
__device__ __half g_Qh[NB * NS * NH];
__device__ __half g_Kh[NB * NS * NH];
__device__ float g_w[NS];
__device__ float g_partial[NB * NB * NMT];

// ---------------- smem layout ----------------
#define O_A   0                       // 64*80 = 5120
#define O_B   5120                    // 256*80 = 20480
#define BUF_SZ 25600
#define O_WS  (2 * BUF_SZ)            // 51200
#define O_KM  (O_WS + 1024)
#define O_QM  (O_KM + 1024)
#define O_MX  (O_QM + 1024)           // [64][4] float = 1024
#define O_SE  (O_MX + 1024)
#define O_SC  (O_SE + 1024)
#define O_RED (O_SC + 1024)
#define SMEM_NEED (O_RED + 64)

// ---------------- PTX helpers (base ISA only) ----------------
__device__ __forceinline__ uint32_t smem_u32(const void* p) {
    uint32_t a;
    asm("{ .reg .u64 t; cvta.to.shared.u64 t, %1; cvt.u32.u64 %0, t; }" : "=r"(a) : "l"(p));
    return a;
}
__device__ __forceinline__ void cpasync16(uint32_t s, const void* g) {
    asm volatile("cp.async.cg.shared.global [%0], [%1], 16;" :: "r"(s), "l"(g));
}
#define CP_COMMIT() asm volatile("cp.async.commit_group;" ::: "memory")
#define CP_WAIT0()  asm volatile("cp.async.wait_group 0;" ::: "memory")
#define CP_WAIT1()  asm volatile("cp.async.wait_group 1;" ::: "memory")

__device__ __forceinline__ void ldsm4(uint32_t (&r)[4], uint32_t a) {
    asm volatile("ldmatrix.sync.aligned.m8n8.x4.shared.b16 {%0,%1,%2,%3}, [%4];"
                 : "=r"(r[0]), "=r"(r[1]), "=r"(r[2]), "=r"(r[3]) : "r"(a));
}
__device__ __forceinline__ void hmma(float* d, const uint32_t (&a)[4],
                                     uint32_t b0, uint32_t b1) {
    asm volatile(
        "mma.sync.aligned.m16n8k16.row.col.f32.f16.f16.f32 "
        "{%0,%1,%2,%3}, {%4,%5,%6,%7}, {%8,%9}, {%0,%1,%2,%3};"
        : "+f"(d[0]), "+f"(d[1]), "+f"(d[2]), "+f"(d[3])
        : "r"(a[0]), "r"(a[1]), "r"(a[2]), "r"(a[3]), "r"(b0), "r"(b1));
}

// ---------------------------------------------------------------------------
__global__ void setup_w_kernel(const float* __restrict__ alpha_raw,
                               const float* __restrict__ logit_scale) {
    float a = alpha_raw[0];
    float alpha = (a > 20.f) ? a : log1pf(expf(a));
    float scale = expf(logit_scale[0]);
    int d = threadIdx.x;
    if (d < NS) g_w[d] = scale * expf(-alpha * (float)d);
}

// L2-normalize one row of 768 -> single fp16
__global__ void norm_kernel(const float* __restrict__ in, int which) {
    __half* dst = which ? g_Kh : g_Qh;
    int r = blockIdx.x;
    int tid = threadIdx.x;
    const float* x = in + (size_t)r * NH;
    float v0 = x[tid], v1 = x[tid + 256], v2 = x[tid + 512];
    float p = v0 * v0 + v1 * v1 + v2 * v2;
    #pragma unroll
    for (int o = 16; o; o >>= 1) p += __shfl_xor_sync(0xffffffffu, p, o);
    __shared__ float red[8];
    __shared__ float inv_s;
    if ((tid & 31) == 0) red[tid >> 5] = p;
    __syncthreads();
    if (tid == 0) {
        float t = 0.f;
        #pragma unroll
        for (int w = 0; w < 8; ++w) t += red[w];
        inv_s = 1.f / fmaxf(sqrtf(t), 1e-12f);
    }
    __syncthreads();
    float inv = inv_s;
    size_t base = (size_t)r * NH;
    dst[base + tid]       = __float2half(v0 * inv);
    dst[base + tid + 256] = __float2half(v1 * inv);
    dst[base + tid + 512] = __float2half(v2 * inv);
}

// ---------------------------------------------------------------------------
// Main: blk = j*128 + i*4 + mt. CTA tile M=64 x N=256, K=768.
// Warps: 2(M) x 4(N), warp tile 32x64. acc[2][8][4] = 64 regs.
// ---------------------------------------------------------------------------
__device__ __forceinline__ void load_chunk(uint32_t sb, int p, int c, int tid,
                                           const __half* Qp, const __half* Kp) {
    int k0 = c * KC;
    uint32_t bufb = sb + p * BUF_SZ;
    // A tile: 64 rows x 4 groups = 256 positions (1/thread)
    {
        int r = tid >> 2, g = tid & 3;
        size_t go = (size_t)r * NH + k0 + g * 8;
        cpasync16(bufb + O_A + (uint32_t)(r * ROWB + g * 16), Qp + go);
    }
    // B tile: 256 rows x 4 groups = 1024 positions (4/thread)
    #pragma unroll
    for (int it = 0; it < 4; ++it) {
        int x = tid + it * 256;
        int r = x >> 2, g = x & 3;
        size_t go = (size_t)r * NH + k0 + g * 8;
        cpasync16(bufb + O_B + (uint32_t)(r * ROWB + g * 16), Kp + go);
    }
    CP_COMMIT();
}

__global__ void __launch_bounds__(256, 2)
li_mma_kernel(const float* __restrict__ qmask, const float* __restrict__ kmask) {
    extern __shared__ char smem[];
    uint32_t sb = smem_u32(smem);

    int tid = threadIdx.x, wid = tid >> 5, lid = tid & 31;
    int warpM = wid >> 2, warpN = wid & 3;
    int blk = blockIdx.x;
    int j = blk >> 7;
    int i = (blk >> 2) & 31;
    int mt = blk & 3;
    int s0 = mt * MT_M;

    float* ws = (float*)(smem + O_WS);
    float* km = (float*)(smem + O_KM);
    float* qm = (float*)(smem + O_QM);
    float* mxs = (float*)(smem + O_MX);   // [64][4]
    float* ses = (float*)(smem + O_SE);
    float* scs = (float*)(smem + O_SC);
    float* red = (float*)(smem + O_RED);
    ws[tid] = g_w[tid];
    km[tid] = kmask[j * NS + tid];
    qm[tid] = qmask[i * NS + tid];

    const __half* Qp = g_Qh + ((size_t)i * NS + s0) * NH;
    const __half* Kp = g_Kh + (size_t)j * NS * NH;

    float acc[2][8][4];
    #pragma unroll
    for (int mf = 0; mf < 2; ++mf)
        #pragma unroll
        for (int nf = 0; nf < 8; ++nf)
            #pragma unroll
            for (int u = 0; u < 4; ++u) acc[mf][nf][u] = 0.f;

    // ldmatrix lane addressing
    // A: row base warpM*32 + mf*16 + lane%16, k-half = lane/16
    uint32_t a_off = (uint32_t)((warpM * 32 + (lid & 15)) * ROWB + ((lid >> 4) << 4));
    // B: row base warpN*64 + nb*16 + b_row
    uint32_t b_row = ((lid >> 4) & 1) * 8 + (lid & 7);
    uint32_t b_off = (uint32_t)((warpN * 64 + b_row) * ROWB + ((lid >> 3) & 1) * 16);

    load_chunk(sb, 0, 0, tid, Qp, Kp);

    for (int c = 0; c < NCHUNK; ++c) {
        int p = c & 1;
        if (c + 1 < NCHUNK) {
            load_chunk(sb, (c + 1) & 1, c + 1, tid, Qp, Kp);
            CP_WAIT1();
        } else {
            CP_WAIT0();
        }
        __syncthreads();

        uint32_t base = sb + p * BUF_SZ;
        #pragma unroll
        for (int ks = 0; ks < 2; ++ks) {
            uint32_t A0[4], A1[4];
            ldsm4(A0, base + O_A + a_off + ks * 32);
            ldsm4(A1, base + O_A + a_off + 16 * ROWB + ks * 32);
            #pragma unroll
            for (int nb = 0; nb < 4; ++nb) {
                uint32_t B[4];
                ldsm4(B, base + O_B + b_off + nb * 16 * ROWB + ks * 32);
                hmma(acc[0][2 * nb],     A0, B[0], B[1]);
                hmma(acc[0][2 * nb + 1], A0, B[2], B[3]);
                hmma(acc[1][2 * nb],     A1, B[0], B[1]);
                hmma(acc[1][2 * nb + 1], A1, B[2], B[3]);
            }
        }
        __syncthreads();   // protect buffer p before chunk c+2 loads overwrite it
    }

    // ---- fused epilogue (rows span 4 N-warps -> smem merge) ----
    int cb = 2 * (lid & 3);
    int rloc = lid >> 2;
    // pass 1: local max per (row, warpN)
    #pragma unroll
    for (int mf = 0; mf < 2; ++mf) {
        #pragma unroll
        for (int half = 0; half < 2; ++half) {
            int row = warpM * 32 + mf * 16 + rloc + half * 8;
            int s = s0 + row;
            float m = -INFINITY;
            #pragma unroll
            for (int nf = 0; nf < 8; ++nf) {
                #pragma unroll
                for (int cc = 0; cc < 2; ++cc) {
                    int t = warpN * 64 + nf * 8 + cb + cc;
                    if (km[t] > 0.f) {
                        int d = s - t; d = d < 0 ? -d : d;
                        m = fmaxf(m, acc[mf][nf][half * 2 + cc] * ws[d]);
                    }
                }
            }
            m = fmaxf(m, __shfl_xor_sync(0xffffffffu, m, 1));
            m = fmaxf(m, __shfl_xor_sync(0xffffffffu, m, 2));
            if ((lid & 3) == 0) mxs[row * 4 + warpN] = m;
        }
    }
    __syncthreads();
    // pass 2: global max, then local se/sec per (row, warpN)
    #pragma unroll
    for (int mf = 0; mf < 2; ++mf) {
        #pragma unroll
        for (int half = 0; half < 2; ++half) {
            int row = warpM * 32 + mf * 16 + rloc + half * 8;
            int s = s0 + row;
            float gmx = fmaxf(fmaxf(mxs[row * 4 + 0], mxs[row * 4 + 1]),
                              fmaxf(mxs[row * 4 + 2], mxs[row * 4 + 3]));
            float se = 0.f, sec = 0.f;
            if (gmx > -INFINITY) {
                #pragma unroll
                for (int nf = 0; nf < 8; ++nf) {
                    #pragma unroll
                    for (int cc = 0; cc < 2; ++cc) {
                        int t = warpN * 64 + nf * 8 + cb + cc;
                        if (km[t] > 0.f) {
                            float sim = acc[mf][nf][half * 2 + cc];
                            int d = s - t; d = d < 0 ? -d : d;
                            float e = __expf(sim * ws[d] - gmx);
                            se += e;
                            sec = fmaf(e, sim, sec);
                        }
                    }
                }
            }
            se  += __shfl_xor_sync(0xffffffffu, se, 1);
            se  += __shfl_xor_sync(0xffffffffu, se, 2);
            sec += __shfl_xor_sync(0xffffffffu, sec, 1);
            sec += __shfl_xor_sync(0xffffffffu, sec, 2);
            if ((lid & 3) == 0) {
                ses[row * 4 + warpN] = se;
                scs[row * 4 + warpN] = sec;
            }
        }
    }
    __syncthreads();
    // pass 3: threads 0..63 finalize one row each
    float rs = 0.f;
    if (tid < MT_M) {
        int row = tid;
        float se = ses[row * 4 + 0] + ses[row * 4 + 1] + ses[row * 4 + 2] + ses[row * 4 + 3];
        float sec = scs[row * 4 + 0] + scs[row * 4 + 1] + scs[row * 4 + 2] + scs[row * 4 + 3];
        float qms = qm[s0 + row];
        if (se > 0.f && qms > 0.f) rs = (sec / se) * qms;
    }
    #pragma unroll
    for (int o = 16; o; o >>= 1) rs += __shfl_xor_sync(0xffffffffu, rs, o);
    if (tid < 64 && lid == 0) red[wid] = rs;
    __syncthreads();
    if (tid == 0) g_partial[blk] = red[0] + red[1];
}

// ---------------------------------------------------------------------------
__global__ void reduce_kernel(const float* __restrict__ qmask, float* __restrict__ out) {
    int i = blockIdx.x;
    int tid = threadIdx.x;
    float v = qmask[i * NS + tid];
    #pragma unroll
    for (int o = 16; o; o >>= 1) v += __shfl_xor_sync(0xffffffffu, v, o);
    __shared__ float red[8];
    __shared__ float qsum_s;
    if ((tid & 31) == 0) red[tid >> 5] = v;
    __syncthreads();
    if (tid == 0) {
        float t = 0.f;
        #pragma unroll
        for (int w = 0; w < 8; ++w) t += red[w];
        qsum_s = fmaxf(t, 1.f);
    }
    __syncthreads();
    if (tid < NB) {
        int jj = tid;
        const float* p = g_partial + jj * 128 + i * 4;
        out[i * NB + jj] = (p[0] + p[1] + p[2] + p[3]) / qsum_s;
    }
}

extern "C" void kernel_launch(void* const* d_in, const int* in_sizes, int n_in,
                              void* d_out, int out_size) {
    const float* q           = (const float*)d_in[0];
    const float* k           = (const float*)d_in[1];
    const float* qmask       = (const float*)d_in[2];
    const float* kmask       = (const float*)d_in[3];
    const float* alpha_raw   = (const float*)d_in[4];
    const float* logit_scale = (const float*)d_in[5];
    float* out = (float*)d_out;

    cudaFuncSetAttribute(li_mma_kernel, cudaFuncAttributeMaxDynamicSharedMemorySize, SMEM_NEED);

    setup_w_kernel<<<1, 256>>>(alpha_raw, logit_scale);
    norm_kernel<<<NB * NS, 256>>>(q, 0);
    norm_kernel<<<NB * NS, 256>>>(k, 1);
    li_mma_kernel<<<NB * NB * NMT, 256, SMEM_NEED>>>(qmask, kmask);
    reduce_kernel<<<NB, 256>>>(qmask, out);
}

// round 7
// speedup vs baseline: 5.6740x; 1.0212x over previous
#include <cuda_runtime.h>
#include <cuda_fp16.h>
#include <math.h>
#include <stdint.h>

#define NB 32
#define NS 256
#define NH 768
#define KC 32
#define NCHUNK (NH / KC)   // 24
#define ROWB 80            // padded smem row stride: 64B data + 16B pad
#define MT_M 64            // M rows per CTA
#define NMT 4              // m-tiles per (i,j)

// ---------------- device scratch ----------------
__device__ __half g_Qh[NB * NS * NH];
__device__ __half g_Kh[NB * NS * NH];
__device__ float g_w[NS];
__device__ float g_partial[NB * NB * NMT];

// ---------------- smem layout (3 buffers) ----------------
#define O_A   0                       // 64*80 = 5120
#define O_B   5120                    // 256*80 = 20480
#define BUF_SZ 25600
#define O_WS  (3 * BUF_SZ)            // 76800
#define O_KM  (O_WS + 1024)
#define O_QM  (O_KM + 1024)
#define O_MX  (O_QM + 1024)           // [64][4] float = 1024
#define O_SE  (O_MX + 1024)
#define O_SC  (O_SE + 1024)
#define O_RED (O_SC + 1024)
#define SMEM_NEED (O_RED + 64)

// ---------------- PTX helpers (base ISA only) ----------------
__device__ __forceinline__ uint32_t smem_u32(const void* p) {
    uint32_t a;
    asm("{ .reg .u64 t; cvta.to.shared.u64 t, %1; cvt.u32.u64 %0, t; }" : "=r"(a) : "l"(p));
    return a;
}
__device__ __forceinline__ void cpasync16(uint32_t s, const void* g) {
    asm volatile("cp.async.cg.shared.global [%0], [%1], 16;" :: "r"(s), "l"(g));
}
#define CP_COMMIT() asm volatile("cp.async.commit_group;" ::: "memory")
#define CP_WAIT0()  asm volatile("cp.async.wait_group 0;" ::: "memory")
#define CP_WAIT1()  asm volatile("cp.async.wait_group 1;" ::: "memory")

__device__ __forceinline__ void ldsm4(uint32_t (&r)[4], uint32_t a) {
    asm volatile("ldmatrix.sync.aligned.m8n8.x4.shared.b16 {%0,%1,%2,%3}, [%4];"
                 : "=r"(r[0]), "=r"(r[1]), "=r"(r[2]), "=r"(r[3]) : "r"(a));
}
__device__ __forceinline__ void hmma(float* d, const uint32_t (&a)[4],
                                     uint32_t b0, uint32_t b1) {
    asm volatile(
        "mma.sync.aligned.m16n8k16.row.col.f32.f16.f16.f32 "
        "{%0,%1,%2,%3}, {%4,%5,%6,%7}, {%8,%9}, {%0,%1,%2,%3};"
        : "+f"(d[0]), "+f"(d[1]), "+f"(d[2]), "+f"(d[3])
        : "r"(a[0]), "r"(a[1]), "r"(a[2]), "r"(a[3]), "r"(b0), "r"(b1));
}

// ---------------------------------------------------------------------------
__global__ void setup_w_kernel(const float* __restrict__ alpha_raw,
                               const float* __restrict__ logit_scale) {
    float a = alpha_raw[0];
    float alpha = (a > 20.f) ? a : log1pf(expf(a));
    float scale = expf(logit_scale[0]);
    int d = threadIdx.x;
    if (d < NS) g_w[d] = scale * expf(-alpha * (float)d);
}

// L2-normalize one row of 768 -> single fp16
__global__ void norm_kernel(const float* __restrict__ in, int which) {
    __half* dst = which ? g_Kh : g_Qh;
    int r = blockIdx.x;
    int tid = threadIdx.x;
    const float* x = in + (size_t)r * NH;
    float v0 = x[tid], v1 = x[tid + 256], v2 = x[tid + 512];
    float p = v0 * v0 + v1 * v1 + v2 * v2;
    #pragma unroll
    for (int o = 16; o; o >>= 1) p += __shfl_xor_sync(0xffffffffu, p, o);
    __shared__ float red[8];
    __shared__ float inv_s;
    if ((tid & 31) == 0) red[tid >> 5] = p;
    __syncthreads();
    if (tid == 0) {
        float t = 0.f;
        #pragma unroll
        for (int w = 0; w < 8; ++w) t += red[w];
        inv_s = 1.f / fmaxf(sqrtf(t), 1e-12f);
    }
    __syncthreads();
    float inv = inv_s;
    size_t base = (size_t)r * NH;
    dst[base + tid]       = __float2half(v0 * inv);
    dst[base + tid + 256] = __float2half(v1 * inv);
    dst[base + tid + 512] = __float2half(v2 * inv);
}

// ---------------------------------------------------------------------------
// Main: blk = j*128 + i*4 + mt. CTA tile M=64 x N=256, K=768.
// Warps: 2(M) x 4(N), warp tile 32x64. acc[2][8][4] = 64 regs.
// 3-stage cp.async ring, ONE barrier per chunk.
// ---------------------------------------------------------------------------
__device__ __forceinline__ void load_chunk(uint32_t sb, int buf, int c, int tid,
                                           const __half* Qp, const __half* Kp) {
    int k0 = c * KC;
    uint32_t bufb = sb + buf * BUF_SZ;
    {   // A tile: 64 rows x 4 groups = 256 positions (1/thread)
        int r = tid >> 2, g = tid & 3;
        size_t go = (size_t)r * NH + k0 + g * 8;
        cpasync16(bufb + O_A + (uint32_t)(r * ROWB + g * 16), Qp + go);
    }
    #pragma unroll
    for (int it = 0; it < 4; ++it) {   // B tile: 1024 positions (4/thread)
        int x = tid + it * 256;
        int r = x >> 2, g = x & 3;
        size_t go = (size_t)r * NH + k0 + g * 8;
        cpasync16(bufb + O_B + (uint32_t)(r * ROWB + g * 16), Kp + go);
    }
    CP_COMMIT();
}

__global__ void __launch_bounds__(256, 2)
li_mma_kernel(const float* __restrict__ qmask, const float* __restrict__ kmask) {
    extern __shared__ char smem[];
    uint32_t sb = smem_u32(smem);

    int tid = threadIdx.x, wid = tid >> 5, lid = tid & 31;
    int warpM = wid >> 2, warpN = wid & 3;
    int blk = blockIdx.x;
    int j = blk >> 7;
    int i = (blk >> 2) & 31;
    int mt = blk & 3;
    int s0 = mt * MT_M;

    float* ws = (float*)(smem + O_WS);
    float* km = (float*)(smem + O_KM);
    float* qm = (float*)(smem + O_QM);
    float* mxs = (float*)(smem + O_MX);   // [64][4]
    float* ses = (float*)(smem + O_SE);
    float* scs = (float*)(smem + O_SC);
    float* red = (float*)(smem + O_RED);
    ws[tid] = g_w[tid];
    km[tid] = kmask[j * NS + tid];
    qm[tid] = qmask[i * NS + tid];

    const __half* Qp = g_Qh + ((size_t)i * NS + s0) * NH;
    const __half* Kp = g_Kh + (size_t)j * NS * NH;

    float acc[2][8][4];
    #pragma unroll
    for (int mf = 0; mf < 2; ++mf)
        #pragma unroll
        for (int nf = 0; nf < 8; ++nf)
            #pragma unroll
            for (int u = 0; u < 4; ++u) acc[mf][nf][u] = 0.f;

    // ldmatrix lane addressing
    uint32_t a_off = (uint32_t)((warpM * 32 + (lid & 15)) * ROWB + ((lid >> 4) << 4));
    uint32_t b_row = ((lid >> 4) & 1) * 8 + (lid & 7);
    uint32_t b_off = (uint32_t)((warpN * 64 + b_row) * ROWB + ((lid >> 3) & 1) * 16);

    // prologue: chunks 0 and 1
    load_chunk(sb, 0, 0, tid, Qp, Kp);
    load_chunk(sb, 1, 1, tid, Qp, Kp);

    int buf = 0;
    for (int c = 0; c < NCHUNK; ++c) {
        if (c + 1 < NCHUNK) { CP_WAIT1(); } else { CP_WAIT0(); }
        __syncthreads();
        // Buffer (c+2)%3 == (c-1)%3 is provably free: every thread passed the
        // barrier above only after finishing compute of chunk c-1.
        if (c + 2 < NCHUNK) {
            int nbuf = buf + 2; if (nbuf >= 3) nbuf -= 3;
            load_chunk(sb, nbuf, c + 2, tid, Qp, Kp);
        }

        uint32_t base = sb + buf * BUF_SZ;
        #pragma unroll
        for (int ks = 0; ks < 2; ++ks) {
            uint32_t A0[4], A1[4];
            ldsm4(A0, base + O_A + a_off + ks * 32);
            ldsm4(A1, base + O_A + a_off + 16 * ROWB + ks * 32);
            #pragma unroll
            for (int nb = 0; nb < 4; ++nb) {
                uint32_t B[4];
                ldsm4(B, base + O_B + b_off + nb * 16 * ROWB + ks * 32);
                hmma(acc[0][2 * nb],     A0, B[0], B[1]);
                hmma(acc[0][2 * nb + 1], A0, B[2], B[3]);
                hmma(acc[1][2 * nb],     A1, B[0], B[1]);
                hmma(acc[1][2 * nb + 1], A1, B[2], B[3]);
            }
        }
        ++buf; if (buf >= 3) buf -= 3;
    }
    __syncthreads();   // acc complete; smem buffers free for epilogue reuse

    // ---- fused epilogue (rows span 4 N-warps -> smem merge) ----
    int cb = 2 * (lid & 3);
    int rloc = lid >> 2;
    // pass 1: local max per (row, warpN)
    #pragma unroll
    for (int mf = 0; mf < 2; ++mf) {
        #pragma unroll
        for (int half = 0; half < 2; ++half) {
            int row = warpM * 32 + mf * 16 + rloc + half * 8;
            int s = s0 + row;
            float m = -INFINITY;
            #pragma unroll
            for (int nf = 0; nf < 8; ++nf) {
                #pragma unroll
                for (int cc = 0; cc < 2; ++cc) {
                    int t = warpN * 64 + nf * 8 + cb + cc;
                    if (km[t] > 0.f) {
                        int d = s - t; d = d < 0 ? -d : d;
                        m = fmaxf(m, acc[mf][nf][half * 2 + cc] * ws[d]);
                    }
                }
            }
            m = fmaxf(m, __shfl_xor_sync(0xffffffffu, m, 1));
            m = fmaxf(m, __shfl_xor_sync(0xffffffffu, m, 2));
            if ((lid & 3) == 0) mxs[row * 4 + warpN] = m;
        }
    }
    __syncthreads();
    // pass 2: global max, then local se/sec per (row, warpN)
    #pragma unroll
    for (int mf = 0; mf < 2; ++mf) {
        #pragma unroll
        for (int half = 0; half < 2; ++half) {
            int row = warpM * 32 + mf * 16 + rloc + half * 8;
            int s = s0 + row;
            float gmx = fmaxf(fmaxf(mxs[row * 4 + 0], mxs[row * 4 + 1]),
                              fmaxf(mxs[row * 4 + 2], mxs[row * 4 + 3]));
            float se = 0.f, sec = 0.f;
            if (gmx > -INFINITY) {
                #pragma unroll
                for (int nf = 0; nf < 8; ++nf) {
                    #pragma unroll
                    for (int cc = 0; cc < 2; ++cc) {
                        int t = warpN * 64 + nf * 8 + cb + cc;
                        if (km[t] > 0.f) {
                            float sim = acc[mf][nf][half * 2 + cc];
                            int d = s - t; d = d < 0 ? -d : d;
                            float e = __expf(sim * ws[d] - gmx);
                            se += e;
                            sec = fmaf(e, sim, sec);
                        }
                    }
                }
            }
            se  += __shfl_xor_sync(0xffffffffu, se, 1);
            se  += __shfl_xor_sync(0xffffffffu, se, 2);
            sec += __shfl_xor_sync(0xffffffffu, sec, 1);
            sec += __shfl_xor_sync(0xffffffffu, sec, 2);
            if ((lid & 3) == 0) {
                ses[row * 4 + warpN] = se;
                scs[row * 4 + warpN] = sec;
            }
        }
    }
    __syncthreads();
    // pass 3: threads 0..63 finalize one row each
    float rs = 0.f;
    if (tid < MT_M) {
        int row = tid;
        float se = ses[row * 4 + 0] + ses[row * 4 + 1] + ses[row * 4 + 2] + ses[row * 4 + 3];
        float sec = scs[row * 4 + 0] + scs[row * 4 + 1] + scs[row * 4 + 2] + scs[row * 4 + 3];
        float qms = qm[s0 + row];
        if (se > 0.f && qms > 0.f) rs = (sec / se) * qms;
    }
    #pragma unroll
    for (int o = 16; o; o >>= 1) rs += __shfl_xor_sync(0xffffffffu, rs, o);
    if (tid < 64 && lid == 0) red[wid] = rs;
    __syncthreads();
    if (tid == 0) g_partial[blk] = red[0] + red[1];
}

// ---------------------------------------------------------------------------
__global__ void reduce_kernel(const float* __restrict__ qmask, float* __restrict__ out) {
    int i = blockIdx.x;
    int tid = threadIdx.x;
    float v = qmask[i * NS + tid];
    #pragma unroll
    for (int o = 16; o; o >>= 1) v += __shfl_xor_sync(0xffffffffu, v, o);
    __shared__ float red[8];
    __shared__ float qsum_s;
    if ((tid & 31) == 0) red[tid >> 5] = v;
    __syncthreads();
    if (tid == 0) {
        float t = 0.f;
        #pragma unroll
        for (int w = 0; w < 8; ++w) t += red[w];
        qsum_s = fmaxf(t, 1.f);
    }
    __syncthreads();
    if (tid < NB) {
        int jj = tid;
        const float* p = g_partial + jj * 128 + i * 4;
        out[i * NB + jj] = (p[0] + p[1] + p[2] + p[3]) / qsum_s;
    }
}

extern "C" void kernel_launch(void* const* d_in, const int* in_sizes, int n_in,
                              void* d_out, int out_size) {
    const float* q           = (const float*)d_in[0];
    const float* k           = (const float*)d_in[1];
    const float* qmask       = (const float*)d_in[2];
    const float* kmask       = (const float*)d_in[3];
    const float* alpha_raw   = (const float*)d_in[4];
    const float* logit_scale = (const float*)d_in[5];
    float* out = (float*)d_out;

    cudaFuncSetAttribute(li_mma_kernel, cudaFuncAttributeMaxDynamicSharedMemorySize, SMEM_NEED);

    setup_w_kernel<<<1, 256>>>(alpha_raw, logit_scale);
    norm_kernel<<<NB * NS, 256>>>(q, 0);
    norm_kernel<<<NB * NS, 256>>>(k, 1);
    li_mma_kernel<<<NB * NB * NMT, 256, SMEM_NEED>>>(qmask, kmask);
    reduce_kernel<<<NB, 256>>>(qmask, out);
}

// round 8
// speedup vs baseline: 5.9777x; 1.0535x over previous
#include <cuda_runtime.h>
#include <cuda_fp16.h>
#include <math.h>
#include <stdint.h>

#define NB 32
#define NS 256
#define NH 768
#define KC 32
#define NCHUNK (NH / KC)   // 24
#define ROWB 80            // padded smem row stride: 64B data + 16B pad
#define MT_M 64            // M rows per CTA
#define NMT 4              // m-tiles per (i,j)

// ---------------- device scratch ----------------
__device__ __half g_Qh[NB * NS * NH];
__device__ __half g_Kh[NB * NS * NH];
__device__ float g_w[NS];
__device__ float g_partial[NB * NB * NMT];

// ---------------- smem layout (3 buffers) ----------------
#define O_A   0                       // 64*80 = 5120
#define O_B   5120                    // 256*80 = 20480
#define BUF_SZ 25600
#define O_WS  (3 * BUF_SZ)            // 76800
#define O_KM  (O_WS + 1024)
#define O_QM  (O_KM + 1024)
#define O_SE  (O_QM + 1024)           // [64][4]
#define O_SC  (O_SE + 1024)
#define O_RED (O_SC + 1024)
#define SMEM_NEED (O_RED + 64)

// ---------------- PTX helpers (base ISA only) ----------------
__device__ __forceinline__ uint32_t smem_u32(const void* p) {
    uint32_t a;
    asm("{ .reg .u64 t; cvta.to.shared.u64 t, %1; cvt.u32.u64 %0, t; }" : "=r"(a) : "l"(p));
    return a;
}
__device__ __forceinline__ void cpasync16(uint32_t s, const void* g) {
    asm volatile("cp.async.cg.shared.global [%0], [%1], 16;" :: "r"(s), "l"(g));
}
#define CP_COMMIT() asm volatile("cp.async.commit_group;" ::: "memory")
#define CP_WAIT0()  asm volatile("cp.async.wait_group 0;" ::: "memory")
#define CP_WAIT1()  asm volatile("cp.async.wait_group 1;" ::: "memory")

__device__ __forceinline__ void ldsm4(uint32_t (&r)[4], uint32_t a) {
    asm volatile("ldmatrix.sync.aligned.m8n8.x4.shared.b16 {%0,%1,%2,%3}, [%4];"
                 : "=r"(r[0]), "=r"(r[1]), "=r"(r[2]), "=r"(r[3]) : "r"(a));
}
__device__ __forceinline__ void hmma(float* d, const uint32_t (&a)[4],
                                     uint32_t b0, uint32_t b1) {
    asm volatile(
        "mma.sync.aligned.m16n8k16.row.col.f32.f16.f16.f32 "
        "{%0,%1,%2,%3}, {%4,%5,%6,%7}, {%8,%9}, {%0,%1,%2,%3};"
        : "+f"(d[0]), "+f"(d[1]), "+f"(d[2]), "+f"(d[3])
        : "r"(a[0]), "r"(a[1]), "r"(a[2]), "r"(a[3]), "r"(b0), "r"(b1));
}

// ---------------------------------------------------------------------------
// One prep kernel: blocks [0, NB*NS) normalize Q rows, [NB*NS, 2*NB*NS) K rows.
// Block 0 additionally builds the decay table g_w.
// ---------------------------------------------------------------------------
__global__ void norm_all_kernel(const float* __restrict__ q, const float* __restrict__ k,
                                const float* __restrict__ alpha_raw,
                                const float* __restrict__ logit_scale) {
    int rb = blockIdx.x;
    int which = rb >= NB * NS;
    int r = which ? rb - NB * NS : rb;
    const float* in = which ? k : q;
    __half* dst = which ? g_Kh : g_Qh;
    int tid = threadIdx.x;

    if (rb == 0 && tid < NS) {
        float a = alpha_raw[0];
        float alpha = (a > 20.f) ? a : log1pf(expf(a));
        float scale = expf(logit_scale[0]);
        g_w[tid] = scale * expf(-alpha * (float)tid);
    }

    const float* x = in + (size_t)r * NH;
    float v0 = x[tid], v1 = x[tid + 256], v2 = x[tid + 512];
    float p = v0 * v0 + v1 * v1 + v2 * v2;
    #pragma unroll
    for (int o = 16; o; o >>= 1) p += __shfl_xor_sync(0xffffffffu, p, o);
    __shared__ float red[8];
    __shared__ float inv_s;
    if ((tid & 31) == 0) red[tid >> 5] = p;
    __syncthreads();
    if (tid == 0) {
        float t = 0.f;
        #pragma unroll
        for (int w = 0; w < 8; ++w) t += red[w];
        inv_s = 1.f / fmaxf(sqrtf(t), 1e-12f);
    }
    __syncthreads();
    float inv = inv_s;
    size_t base = (size_t)r * NH;
    dst[base + tid]       = __float2half(v0 * inv);
    dst[base + tid + 256] = __float2half(v1 * inv);
    dst[base + tid + 512] = __float2half(v2 * inv);
}

// ---------------------------------------------------------------------------
// Main: blk = j*128 + i*4 + mt. CTA tile M=64 x N=256, K=768.
// Warps: 2(M) x 4(N), warp tile 32x64. acc[2][8][4] = 64 regs.
// 3-stage cp.async ring, ONE barrier per chunk, software-pipelined ldsm.
// ---------------------------------------------------------------------------
__device__ __forceinline__ void load_chunk(uint32_t sb, int buf, int c, int tid,
                                           const __half* Qp, const __half* Kp) {
    int k0 = c * KC;
    uint32_t bufb = sb + buf * BUF_SZ;
    {   // A tile: 64 rows x 4 groups = 256 positions (1/thread)
        int r = tid >> 2, g = tid & 3;
        size_t go = (size_t)r * NH + k0 + g * 8;
        cpasync16(bufb + O_A + (uint32_t)(r * ROWB + g * 16), Qp + go);
    }
    #pragma unroll
    for (int it = 0; it < 4; ++it) {   // B tile: 1024 positions (4/thread)
        int x = tid + it * 256;
        int r = x >> 2, g = x & 3;
        size_t go = (size_t)r * NH + k0 + g * 8;
        cpasync16(bufb + O_B + (uint32_t)(r * ROWB + g * 16), Kp + go);
    }
    CP_COMMIT();
}

__global__ void __launch_bounds__(256, 2)
li_mma_kernel(const float* __restrict__ qmask, const float* __restrict__ kmask) {
    extern __shared__ char smem[];
    uint32_t sb = smem_u32(smem);

    int tid = threadIdx.x, wid = tid >> 5, lid = tid & 31;
    int warpM = wid >> 2, warpN = wid & 3;
    int blk = blockIdx.x;
    int j = blk >> 7;
    int i = (blk >> 2) & 31;
    int mt = blk & 3;
    int s0 = mt * MT_M;

    float* ws = (float*)(smem + O_WS);
    float* km = (float*)(smem + O_KM);
    float* qm = (float*)(smem + O_QM);
    float* ses = (float*)(smem + O_SE);
    float* scs = (float*)(smem + O_SC);
    float* red = (float*)(smem + O_RED);
    ws[tid] = g_w[tid];
    km[tid] = kmask[j * NS + tid];
    qm[tid] = qmask[i * NS + tid];

    const __half* Qp = g_Qh + ((size_t)i * NS + s0) * NH;
    const __half* Kp = g_Kh + (size_t)j * NS * NH;

    float acc[2][8][4];
    #pragma unroll
    for (int mf = 0; mf < 2; ++mf)
        #pragma unroll
        for (int nf = 0; nf < 8; ++nf)
            #pragma unroll
            for (int u = 0; u < 4; ++u) acc[mf][nf][u] = 0.f;

    // ldmatrix lane addressing
    uint32_t a_off = (uint32_t)((warpM * 32 + (lid & 15)) * ROWB + ((lid >> 4) << 4));
    uint32_t b_row = ((lid >> 4) & 1) * 8 + (lid & 7);
    uint32_t b_off = (uint32_t)((warpN * 64 + b_row) * ROWB + ((lid >> 3) & 1) * 16);

    // prologue: chunks 0 and 1
    load_chunk(sb, 0, 0, tid, Qp, Kp);
    load_chunk(sb, 1, 1, tid, Qp, Kp);

    int buf = 0;
    for (int c = 0; c < NCHUNK; ++c) {
        if (c + 1 < NCHUNK) { CP_WAIT1(); } else { CP_WAIT0(); }
        __syncthreads();
        // Buffer (c+2)%3 == (c-1)%3 is provably free after the barrier.
        if (c + 2 < NCHUNK) {
            int nbuf = buf + 2; if (nbuf >= 3) nbuf -= 3;
            load_chunk(sb, nbuf, c + 2, tid, Qp, Kp);
        }

        uint32_t base = sb + buf * BUF_SZ;
        // software-pipelined fragment loads: A for both ks hoisted, B double-buffered
        uint32_t A0[2][4], A1[2][4], Bf[2][4];
        ldsm4(A0[0], base + O_A + a_off);
        ldsm4(A1[0], base + O_A + a_off + 16 * ROWB);
        ldsm4(Bf[0], base + O_B + b_off);
        ldsm4(A0[1], base + O_A + a_off + 32);
        ldsm4(A1[1], base + O_A + a_off + 16 * ROWB + 32);
        #pragma unroll
        for (int t = 0; t < 8; ++t) {
            int ks = t >> 2, nb = t & 3;
            int cur = t & 1;
            if (t < 7) {
                int t1 = t + 1, ks1 = t1 >> 2, nb1 = t1 & 3;
                ldsm4(Bf[cur ^ 1], base + O_B + b_off + nb1 * 16 * ROWB + ks1 * 32);
            }
            hmma(acc[0][2 * nb],     A0[ks], Bf[cur][0], Bf[cur][1]);
            hmma(acc[0][2 * nb + 1], A0[ks], Bf[cur][2], Bf[cur][3]);
            hmma(acc[1][2 * nb],     A1[ks], Bf[cur][0], Bf[cur][1]);
            hmma(acc[1][2 * nb + 1], A1[ks], Bf[cur][2], Bf[cur][3]);
        }
        ++buf; if (buf >= 3) buf -= 3;
    }
    __syncthreads();   // acc complete

    // ---- fused epilogue, single pass (softmax shifted by constant w[0]) ----
    // Shift-invariance: logits = sim*w[d] <= w[0] (|sim|<=1, decay<=1), so the
    // fixed shift w[0] is a valid softmax offset; no per-row max needed.
    float shift = ws[0];
    int cb = 2 * (lid & 3);
    int rloc = lid >> 2;
    #pragma unroll
    for (int mf = 0; mf < 2; ++mf) {
        #pragma unroll
        for (int half = 0; half < 2; ++half) {
            int row = warpM * 32 + mf * 16 + rloc + half * 8;
            int s = s0 + row;
            float se = 0.f, sec = 0.f;
            #pragma unroll
            for (int nf = 0; nf < 8; ++nf) {
                #pragma unroll
                for (int cc = 0; cc < 2; ++cc) {
                    int t = warpN * 64 + nf * 8 + cb + cc;
                    if (km[t] > 0.f) {
                        float sim = acc[mf][nf][half * 2 + cc];
                        int d = s - t; d = d < 0 ? -d : d;
                        float e = __expf(sim * ws[d] - shift);
                        se += e;
                        sec = fmaf(e, sim, sec);
                    }
                }
            }
            se  += __shfl_xor_sync(0xffffffffu, se, 1);
            se  += __shfl_xor_sync(0xffffffffu, se, 2);
            sec += __shfl_xor_sync(0xffffffffu, sec, 1);
            sec += __shfl_xor_sync(0xffffffffu, sec, 2);
            if ((lid & 3) == 0) {
                ses[row * 4 + warpN] = se;
                scs[row * 4 + warpN] = sec;
            }
        }
    }
    __syncthreads();
    // finalize: threads 0..63, one row each
    float rs = 0.f;
    if (tid < MT_M) {
        int row = tid;
        float se = ses[row * 4 + 0] + ses[row * 4 + 1] + ses[row * 4 + 2] + ses[row * 4 + 3];
        float sec = scs[row * 4 + 0] + scs[row * 4 + 1] + scs[row * 4 + 2] + scs[row * 4 + 3];
        float qms = qm[s0 + row];
        if (se > 0.f && qms > 0.f) rs = (sec / se) * qms;
    }
    #pragma unroll
    for (int o = 16; o; o >>= 1) rs += __shfl_xor_sync(0xffffffffu, rs, o);
    if (tid < 64 && lid == 0) red[wid] = rs;
    __syncthreads();
    if (tid == 0) g_partial[blk] = red[0] + red[1];
}

// ---------------------------------------------------------------------------
__global__ void reduce_kernel(const float* __restrict__ qmask, float* __restrict__ out) {
    int i = blockIdx.x;
    int tid = threadIdx.x;
    float v = qmask[i * NS + tid];
    #pragma unroll
    for (int o = 16; o; o >>= 1) v += __shfl_xor_sync(0xffffffffu, v, o);
    __shared__ float red[8];
    __shared__ float qsum_s;
    if ((tid & 31) == 0) red[tid >> 5] = v;
    __syncthreads();
    if (tid == 0) {
        float t = 0.f;
        #pragma unroll
        for (int w = 0; w < 8; ++w) t += red[w];
        qsum_s = fmaxf(t, 1.f);
    }
    __syncthreads();
    if (tid < NB) {
        int jj = tid;
        const float* p = g_partial + jj * 128 + i * 4;
        out[i * NB + jj] = (p[0] + p[1] + p[2] + p[3]) / qsum_s;
    }
}

extern "C" void kernel_launch(void* const* d_in, const int* in_sizes, int n_in,
                              void* d_out, int out_size) {
    const float* q           = (const float*)d_in[0];
    const float* k           = (const float*)d_in[1];
    const float* qmask       = (const float*)d_in[2];
    const float* kmask       = (const float*)d_in[3];
    const float* alpha_raw   = (const float*)d_in[4];
    const float* logit_scale = (const float*)d_in[5];
    float* out = (float*)d_out;

    cudaFuncSetAttribute(li_mma_kernel, cudaFuncAttributeMaxDynamicSharedMemorySize, SMEM_NEED);

    norm_all_kernel<<<2 * NB * NS, 256>>>(q, k, alpha_raw, logit_scale);
    li_mma_kernel<<<NB * NB * NMT, 256, SMEM_NEED>>>(qmask, kmask);
    reduce_kernel<<<NB, 256>>>(qmask, out);
}

// round 9
// speedup vs baseline: 7.2676x; 1.2158x over previous
#include <cuda_runtime.h>
#include <cuda_fp16.h>
#include <math.h>
#include <stdint.h>

#define NB 32
#define NS 256
#define NH 768
#define KC 64
#define NCHUNK (NH / KC)   // 12
#define ROWB 144           // padded smem row stride: 128B data + 16B pad
#define MT_M 64            // M rows per CTA
#define NMT 4              // m-tiles per (i,j)

// ---------------- device scratch ----------------
__device__ __half g_Qh[NB * NS * NH];
__device__ __half g_Kh[NB * NS * NH];
__device__ float g_w[NS];
__device__ float g_partial[NB * NB * NMT];

// ---------------- smem layout (2 buffers) ----------------
#define O_A   0                       // 64*144 = 9216
#define O_B   9216                    // 256*144 = 36864
#define BUF_SZ 46080
#define O_WS  (2 * BUF_SZ)            // 92160
#define O_KM  (O_WS + 1024)
#define O_QM  (O_KM + 1024)
#define O_SE  (O_QM + 1024)           // [64][4]
#define O_SC  (O_SE + 1024)
#define O_RED (O_SC + 1024)
#define SMEM_NEED (O_RED + 64)

// ---------------- PTX helpers (base ISA only) ----------------
__device__ __forceinline__ uint32_t smem_u32(const void* p) {
    uint32_t a;
    asm("{ .reg .u64 t; cvta.to.shared.u64 t, %1; cvt.u32.u64 %0, t; }" : "=r"(a) : "l"(p));
    return a;
}
__device__ __forceinline__ void cpasync16(uint32_t s, const void* g) {
    asm volatile("cp.async.cg.shared.global [%0], [%1], 16;" :: "r"(s), "l"(g));
}
#define CP_COMMIT() asm volatile("cp.async.commit_group;" ::: "memory")
#define CP_WAIT0()  asm volatile("cp.async.wait_group 0;" ::: "memory")

__device__ __forceinline__ void ldsm4(uint32_t (&r)[4], uint32_t a) {
    asm volatile("ldmatrix.sync.aligned.m8n8.x4.shared.b16 {%0,%1,%2,%3}, [%4];"
                 : "=r"(r[0]), "=r"(r[1]), "=r"(r[2]), "=r"(r[3]) : "r"(a));
}
__device__ __forceinline__ void hmma(float* d, const uint32_t (&a)[4],
                                     uint32_t b0, uint32_t b1) {
    asm volatile(
        "mma.sync.aligned.m16n8k16.row.col.f32.f16.f16.f32 "
        "{%0,%1,%2,%3}, {%4,%5,%6,%7}, {%8,%9}, {%0,%1,%2,%3};"
        : "+f"(d[0]), "+f"(d[1]), "+f"(d[2]), "+f"(d[3])
        : "r"(a[0]), "r"(a[1]), "r"(a[2]), "r"(a[3]), "r"(b0), "r"(b1));
}

// ---------------------------------------------------------------------------
// Prep: one WARP per row, no block barriers. Blocks of 8 warps.
// Rows [0, 8192) -> Q, [8192, 16384) -> K. Block 0 also builds g_w.
// ---------------------------------------------------------------------------
__global__ void __launch_bounds__(256)
norm_all_kernel(const float* __restrict__ q, const float* __restrict__ k,
                const float* __restrict__ alpha_raw,
                const float* __restrict__ logit_scale) {
    int tid = threadIdx.x, wid = tid >> 5, lid = tid & 31;

    if (blockIdx.x == 0) {
        float a = alpha_raw[0];
        float alpha = (a > 20.f) ? a : log1pf(expf(a));
        float scale = expf(logit_scale[0]);
        g_w[tid] = scale * expf(-alpha * (float)tid);
    }

    int row = blockIdx.x * 8 + wid;          // 0..16383
    int which = row >= NB * NS;
    int r = which ? row - NB * NS : row;
    const float4* x = (const float4*)((which ? k : q) + (size_t)r * NH);

    float4 v[6];
    float ss = 0.f;
    #pragma unroll
    for (int t = 0; t < 6; ++t) {
        v[t] = x[lid + 32 * t];
        ss += v[t].x * v[t].x + v[t].y * v[t].y + v[t].z * v[t].z + v[t].w * v[t].w;
    }
    #pragma unroll
    for (int o = 16; o; o >>= 1) ss += __shfl_xor_sync(0xffffffffu, ss, o);
    float inv = 1.f / fmaxf(sqrtf(ss), 1e-12f);

    __half2* dst = (__half2*)((which ? g_Kh : g_Qh) + (size_t)r * NH);
    #pragma unroll
    for (int t = 0; t < 6; ++t) {
        int h2 = 2 * (lid + 32 * t);
        dst[h2]     = __floats2half2_rn(v[t].x * inv, v[t].y * inv);
        dst[h2 + 1] = __floats2half2_rn(v[t].z * inv, v[t].w * inv);
    }
}

// ---------------------------------------------------------------------------
// Main: blk = j*128 + i*4 + mt. CTA tile M=64 x N=256, K=768.
// Warps: 2(M) x 4(N), warp tile 32x64. acc[2][8][4] = 64 regs.
// KC=64 chunks, 2-buffer ring, ONE barrier per chunk (12 total).
// ---------------------------------------------------------------------------
__device__ __forceinline__ void load_chunk(uint32_t sb, int buf, int c, int tid,
                                           const __half* Qp, const __half* Kp) {
    int k0 = c * KC;
    uint32_t bufb = sb + buf * BUF_SZ;
    #pragma unroll
    for (int it = 0; it < 2; ++it) {   // A tile: 64 rows x 8 groups = 512 (2/thread)
        int x = tid + it * 256;
        int r = x >> 3, g = x & 7;
        size_t go = (size_t)r * NH + k0 + g * 8;
        cpasync16(bufb + O_A + (uint32_t)(r * ROWB + g * 16), Qp + go);
    }
    #pragma unroll
    for (int it = 0; it < 8; ++it) {   // B tile: 256 rows x 8 groups = 2048 (8/thread)
        int x = tid + it * 256;
        int r = x >> 3, g = x & 7;
        size_t go = (size_t)r * NH + k0 + g * 8;
        cpasync16(bufb + O_B + (uint32_t)(r * ROWB + g * 16), Kp + go);
    }
    CP_COMMIT();
}

__global__ void __launch_bounds__(256, 2)
li_mma_kernel(const float* __restrict__ qmask, const float* __restrict__ kmask) {
    extern __shared__ char smem[];
    uint32_t sb = smem_u32(smem);

    int tid = threadIdx.x, wid = tid >> 5, lid = tid & 31;
    int warpM = wid >> 2, warpN = wid & 3;
    int blk = blockIdx.x;
    int j = blk >> 7;
    int i = (blk >> 2) & 31;
    int mt = blk & 3;
    int s0 = mt * MT_M;

    float* ws = (float*)(smem + O_WS);
    float* km = (float*)(smem + O_KM);
    float* qm = (float*)(smem + O_QM);
    float* ses = (float*)(smem + O_SE);
    float* scs = (float*)(smem + O_SC);
    float* red = (float*)(smem + O_RED);
    ws[tid] = g_w[tid];
    km[tid] = kmask[j * NS + tid];
    qm[tid] = qmask[i * NS + tid];

    const __half* Qp = g_Qh + ((size_t)i * NS + s0) * NH;
    const __half* Kp = g_Kh + (size_t)j * NS * NH;

    float acc[2][8][4];
    #pragma unroll
    for (int mf = 0; mf < 2; ++mf)
        #pragma unroll
        for (int nf = 0; nf < 8; ++nf)
            #pragma unroll
            for (int u = 0; u < 4; ++u) acc[mf][nf][u] = 0.f;

    // ldmatrix lane addressing
    uint32_t a_off = (uint32_t)((warpM * 32 + (lid & 15)) * ROWB + ((lid >> 4) << 4));
    uint32_t b_row = ((lid >> 4) & 1) * 8 + (lid & 7);
    uint32_t b_off = (uint32_t)((warpN * 64 + b_row) * ROWB + ((lid >> 3) & 1) * 16);

    load_chunk(sb, 0, 0, tid, Qp, Kp);

    for (int c = 0; c < NCHUNK; ++c) {
        CP_WAIT0();           // chunk c fully in smem
        __syncthreads();      // all threads done computing chunk c-1, see chunk c
        if (c + 1 < NCHUNK)   // prefetch into the other buffer (chunk c-1's, now free)
            load_chunk(sb, (c + 1) & 1, c + 1, tid, Qp, Kp);

        uint32_t base = sb + (c & 1) * BUF_SZ;
        #pragma unroll
        for (int kh = 0; kh < 2; ++kh) {   // two k32 groups per chunk
            uint32_t kb = kh * 64;         // byte offset of this k32 group
            uint32_t A0[2][4], A1[2][4], Bf[2][4];
            ldsm4(A0[0], base + O_A + a_off + kb);
            ldsm4(A1[0], base + O_A + a_off + 16 * ROWB + kb);
            ldsm4(Bf[0], base + O_B + b_off + kb);
            ldsm4(A0[1], base + O_A + a_off + kb + 32);
            ldsm4(A1[1], base + O_A + a_off + 16 * ROWB + kb + 32);
            #pragma unroll
            for (int t = 0; t < 8; ++t) {
                int ks = t >> 2, nb = t & 3;
                int cur = t & 1;
                if (t < 7) {
                    int t1 = t + 1, ks1 = t1 >> 2, nb1 = t1 & 3;
                    ldsm4(Bf[cur ^ 1], base + O_B + b_off + nb1 * 16 * ROWB + kb + ks1 * 32);
                }
                hmma(acc[0][2 * nb],     A0[ks], Bf[cur][0], Bf[cur][1]);
                hmma(acc[0][2 * nb + 1], A0[ks], Bf[cur][2], Bf[cur][3]);
                hmma(acc[1][2 * nb],     A1[ks], Bf[cur][0], Bf[cur][1]);
                hmma(acc[1][2 * nb + 1], A1[ks], Bf[cur][2], Bf[cur][3]);
            }
        }
    }
    __syncthreads();   // acc complete

    // ---- fused epilogue, single pass (softmax shifted by constant w[0]) ----
    float shift = ws[0];
    int cb = 2 * (lid & 3);
    int rloc = lid >> 2;
    #pragma unroll
    for (int mf = 0; mf < 2; ++mf) {
        #pragma unroll
        for (int half = 0; half < 2; ++half) {
            int row = warpM * 32 + mf * 16 + rloc + half * 8;
            int s = s0 + row;
            float se = 0.f, sec = 0.f;
            #pragma unroll
            for (int nf = 0; nf < 8; ++nf) {
                #pragma unroll
                for (int cc = 0; cc < 2; ++cc) {
                    int t = warpN * 64 + nf * 8 + cb + cc;
                    if (km[t] > 0.f) {
                        float sim = acc[mf][nf][half * 2 + cc];
                        int d = s - t; d = d < 0 ? -d : d;
                        float e = __expf(sim * ws[d] - shift);
                        se += e;
                        sec = fmaf(e, sim, sec);
                    }
                }
            }
            se  += __shfl_xor_sync(0xffffffffu, se, 1);
            se  += __shfl_xor_sync(0xffffffffu, se, 2);
            sec += __shfl_xor_sync(0xffffffffu, sec, 1);
            sec += __shfl_xor_sync(0xffffffffu, sec, 2);
            if ((lid & 3) == 0) {
                ses[row * 4 + warpN] = se;
                scs[row * 4 + warpN] = sec;
            }
        }
    }
    __syncthreads();
    float rs = 0.f;
    if (tid < MT_M) {
        int row = tid;
        float se = ses[row * 4 + 0] + ses[row * 4 + 1] + ses[row * 4 + 2] + ses[row * 4 + 3];
        float sec = scs[row * 4 + 0] + scs[row * 4 + 1] + scs[row * 4 + 2] + scs[row * 4 + 3];
        float qms = qm[s0 + row];
        if (se > 0.f && qms > 0.f) rs = (sec / se) * qms;
    }
    #pragma unroll
    for (int o = 16; o; o >>= 1) rs += __shfl_xor_sync(0xffffffffu, rs, o);
    if (tid < 64 && lid == 0) red[wid] = rs;
    __syncthreads();
    if (tid == 0) g_partial[blk] = red[0] + red[1];
}

// ---------------------------------------------------------------------------
__global__ void reduce_kernel(const float* __restrict__ qmask, float* __restrict__ out) {
    int i = blockIdx.x;
    int tid = threadIdx.x;
    float v = qmask[i * NS + tid];
    #pragma unroll
    for (int o = 16; o; o >>= 1) v += __shfl_xor_sync(0xffffffffu, v, o);
    __shared__ float red[8];
    __shared__ float qsum_s;
    if ((tid & 31) == 0) red[tid >> 5] = v;
    __syncthreads();
    if (tid == 0) {
        float t = 0.f;
        #pragma unroll
        for (int w = 0; w < 8; ++w) t += red[w];
        qsum_s = fmaxf(t, 1.f);
    }
    __syncthreads();
    if (tid < NB) {
        int jj = tid;
        const float* p = g_partial + jj * 128 + i * 4;
        out[i * NB + jj] = (p[0] + p[1] + p[2] + p[3]) / qsum_s;
    }
}

extern "C" void kernel_launch(void* const* d_in, const int* in_sizes, int n_in,
                              void* d_out, int out_size) {
    const float* q           = (const float*)d_in[0];
    const float* k           = (const float*)d_in[1];
    const float* qmask       = (const float*)d_in[2];
    const float* kmask       = (const float*)d_in[3];
    const float* alpha_raw   = (const float*)d_in[4];
    const float* logit_scale = (const float*)d_in[5];
    float* out = (float*)d_out;

    cudaFuncSetAttribute(li_mma_kernel, cudaFuncAttributeMaxDynamicSharedMemorySize, SMEM_NEED);

    norm_all_kernel<<<2 * NB * NS / 8, 256>>>(q, k, alpha_raw, logit_scale);
    li_mma_kernel<<<NB * NB * NMT, 256, SMEM_NEED>>>(qmask, kmask);
    reduce_kernel<<<NB, 256>>>(qmask, out);
}